// round 6
// baseline (speedup 1.0000x reference)
#include <cuda_runtime.h>
#include <math.h>
#include <stdint.h>

#define NEG_SLOPE 0.2f
#define LOG2E 1.4426950408889634f

// Problem constants
#define BS 32
#define NA 512          // n_agents
#define ID 128          // input_dim
#define NH 8            // n_heads
#define HD 64           // hidden_dim

// h_prime^T scratch: [b][head][d][m] = 32*8*64*512 floats = 33.5 MB
__device__ float g_hpT[BS * NH * HD * NA];

// ---------------------------------------------------------------------------
// helpers
// ---------------------------------------------------------------------------
__device__ __forceinline__ float to_tf32(float x) {
    uint32_t u;
    asm("cvt.rn.tf32.f32 %0, %1;" : "=r"(u) : "f"(x));
    return __uint_as_float(u);
}
__device__ __forceinline__ float ex2(float x) {
    float r;
    asm("ex2.approx.f32 %0, %1;" : "=f"(r) : "f"(x));
    return r;
}
__device__ __forceinline__ void mma_tf32(float d[4], float a0, float a1,
                                         float a2, float a3, float b0, float b1) {
    asm volatile(
        "mma.sync.aligned.m16n8k8.row.col.f32.tf32.tf32.f32 "
        "{%0,%1,%2,%3}, {%4,%5,%6,%7}, {%8,%9}, {%0,%1,%2,%3};"
        : "+f"(d[0]), "+f"(d[1]), "+f"(d[2]), "+f"(d[3])
        : "r"(__float_as_uint(a0)), "r"(__float_as_uint(a1)),
          "r"(__float_as_uint(a2)), "r"(__float_as_uint(a3)),
          "r"(__float_as_uint(b0)), "r"(__float_as_uint(b1)));
}

// ---------------------------------------------------------------------------
// Kernel A: g_hpT[b][head][d][m] = (Wt @ h^T) via split-tf32 mma (3 products).
// CTA = (b, head, n-quarter of 128 rows). 256 threads = 8 warps = 4 mt x 2 nh.
// A = W^T [64 d][128 k] (hi/lo), B = h [128 n][128 k] (hi/lo, col-major over k).
// ---------------------------------------------------------------------------
#define G_PAD 4
#define WT_S (ID + G_PAD)   // 132
#define H_S  (ID + G_PAD)   // 132
#define SMEM_G_FLOATS (2 * 64 * WT_S + 2 * 128 * H_S)
#define SMEM_G_BYTES (SMEM_G_FLOATS * 4)

__global__ void __launch_bounds__(256, 1) gemm_hp_tc(
    const float* __restrict__ h, const float* __restrict__ W)
{
    extern __shared__ float smg[];
    float* Wt_hi = smg;
    float* Wt_lo = Wt_hi + 64 * WT_S;
    float* h_hi  = Wt_lo + 64 * WT_S;
    float* h_lo  = h_hi + 128 * H_S;

    const int tid = threadIdx.x;
    const int bxx = blockIdx.x;
    const int b    = bxx >> 5;
    const int head = (bxx >> 2) & 7;
    const int nq   = bxx & 3;
    const int n0   = nq * 128;
    const int col0 = head * HD;

    // Stage W^T (hi/lo): elem (d, k); coalesced LDG over d.
    #pragma unroll 4
    for (int i = 0; i < 32; i++) {
        int t = tid + i * 256;
        int d = t & 63, k = t >> 6;
        float v = W[(size_t)k * 512 + col0 + d];
        float hi = to_tf32(v);
        Wt_hi[d * WT_S + k] = hi;
        Wt_lo[d * WT_S + k] = to_tf32(v - hi);
    }
    // Stage h rows [n0, n0+128) (hi/lo), float4.
    #pragma unroll 4
    for (int i = 0; i < 16; i++) {
        int t = tid + i * 256;
        int n = t >> 5, kq = t & 31;
        float4 v = *(const float4*)&h[((size_t)(b * NA + n0 + n)) * ID + kq * 4];
        float4 hi4, lo4;
        hi4.x = to_tf32(v.x); lo4.x = to_tf32(v.x - hi4.x);
        hi4.y = to_tf32(v.y); lo4.y = to_tf32(v.y - hi4.y);
        hi4.z = to_tf32(v.z); lo4.z = to_tf32(v.z - hi4.z);
        hi4.w = to_tf32(v.w); lo4.w = to_tf32(v.w - hi4.w);
        *(float4*)&h_hi[n * H_S + kq * 4] = hi4;
        *(float4*)&h_lo[n * H_S + kq * 4] = lo4;
    }
    __syncthreads();

    const int warp = tid >> 5;
    const int lane = tid & 31;
    const int q = lane >> 2;
    const int c = lane & 3;
    const int mt = warp >> 1;    // d-tile (0..3): rows mt*16 + {q, q+8}
    const int nh = warp & 1;     // n-half (0..1): 8 n8-fragments

    float acc[8][4];
    #pragma unroll
    for (int f = 0; f < 8; f++)
        #pragma unroll
        for (int j = 0; j < 4; j++) acc[f][j] = 0.f;

    const float* wa_hi = Wt_hi + (mt * 16 + q) * WT_S + 2 * c;
    const float* wa_lo = Wt_lo + (mt * 16 + q) * WT_S + 2 * c;
    const float* hb_hi = h_hi + (nh * 64 + q) * H_S + 2 * c;
    const float* hb_lo = h_lo + (nh * 64 + q) * H_S + 2 * c;

    #pragma unroll 4
    for (int k8 = 0; k8 < 16; k8++) {
        const int ko = k8 * 8;
        // A fragments (k-permuted: phys c,c+4 -> logical 2c,2c+1; consistent with B)
        float2 ah0 = *(const float2*)&wa_hi[ko];
        float2 ah1 = *(const float2*)&wa_hi[8 * WT_S + ko];
        float2 al0 = *(const float2*)&wa_lo[ko];
        float2 al1 = *(const float2*)&wa_lo[8 * WT_S + ko];
        #pragma unroll
        for (int nf = 0; nf < 8; nf++) {
            float2 bh = *(const float2*)&hb_hi[nf * 8 * H_S + ko];
            float2 bl = *(const float2*)&hb_lo[nf * 8 * H_S + ko];
            mma_tf32(acc[nf], ah0.x, ah1.x, ah0.y, ah1.y, bh.x, bh.y); // hi*hi
            mma_tf32(acc[nf], al0.x, al1.x, al0.y, al1.y, bh.x, bh.y); // lo*hi
            mma_tf32(acc[nf], ah0.x, ah1.x, ah0.y, ah1.y, bl.x, bl.y); // hi*lo
        }
    }

    // Epilogue: D[d][n] -> g_hpT rows dg, dg+8
    const int dg = mt * 16 + q;
    float* og = g_hpT + ((size_t)(b * NH + head) * HD + dg) * NA + n0 + nh * 64 + 2 * c;
    #pragma unroll
    for (int nf = 0; nf < 8; nf++) {
        *(float2*)&og[nf * 8]          = make_float2(acc[nf][0], acc[nf][1]);
        *(float2*)&og[8 * NA + nf * 8] = make_float2(acc[nf][2], acc[nf][3]);
    }
}

// ---------------------------------------------------------------------------
// Kernel B: mma.sync tf32 attention. 512 threads, 16 warps = 8 rowgrp x 2 dh.
// Grid: 2 CTAs per (b,h), 256 n-rows each, full 512-m scan.
// Warp: 32 rows (2 m16 tiles) x 32 d-cols (4 n8 frags, its d-half).
// ---------------------------------------------------------------------------
#define HPT_S 516
#define SM_HPT   0
#define SM_ED    (64 * HPT_S)            // [512]
#define SM_ED02  (SM_ED + 512)           // [512]
#define SM_ES    (SM_ED02 + 512)         // [256]
#define SM_ES02  (SM_ES + 256)           // [256]
#define SM_A     (SM_ES02 + 256)         // [128]
#define SMEM_B_FLOATS (SM_A + 128)
#define SMEM_B_BYTES (SMEM_B_FLOATS * 4)

__device__ __forceinline__ float elu1(float x) {
    return x > 0.f ? x : expm1f(x);
}

__global__ void __launch_bounds__(512, 1) attn_mma_kernel(
    const float* __restrict__ att_a, float* __restrict__ out)
{
    extern __shared__ float sm[];
    float* hpT    = sm + SM_HPT;
    float* Ed_s   = sm + SM_ED;
    float* Ed02_s = sm + SM_ED02;
    float* Es_s   = sm + SM_ES;
    float* Es02_s = sm + SM_ES02;
    float* a_s    = sm + SM_A;

    const int bx = blockIdx.x;
    const int bh = bx >> 1;
    const int head = bh & 7;
    const int nbase = (bx & 1) * 256;
    const int tid = threadIdx.x;
    const int warp = tid >> 5;
    const int lane = tid & 31;
    const int q = lane >> 2;       // group id
    const int c = lane & 3;        // k position / col pair

    if (tid < 128) a_s[tid] = att_a[head * 128 + tid];

    // Stage hpT (tf32-rounded) into padded SMEM
    const float* hg = g_hpT + (size_t)bh * HD * NA;
    #pragma unroll 4
    for (int i = 0; i < 16; i++) {
        int f = tid + i * 512;           // 8192 float4s
        int d = f >> 7;
        int mq = f & 127;
        float4 v = *(const float4*)&hg[(size_t)d * NA + mq * 4];
        v.x = to_tf32(v.x); v.y = to_tf32(v.y);
        v.z = to_tf32(v.z); v.w = to_tf32(v.w);
        *(float4*)&hpT[d * HPT_S + mq * 4] = v;
    }
    __syncthreads();

    // e-scores: Ed for all m, Es for this CTA's 256 rows. One m per thread.
    {
        const int m = tid;
        float es = 0.f, ed = 0.f;
        #pragma unroll
        for (int d = 0; d < 64; d++) {
            float hp = hpT[d * HPT_S + m];
            es += hp * a_s[d];
            ed += hp * a_s[64 + d];
        }
        Ed_s[m]   = ex2(ed * LOG2E);
        Ed02_s[m] = ex2(ed * (NEG_SLOPE * LOG2E));
        int r = m - nbase;
        if ((unsigned)r < 256u) {
            Es_s[r]   = ex2(es * LOG2E);
            Es02_s[r] = ex2(es * (NEG_SLOPE * LOG2E));
        }
    }
    __syncthreads();

    const int rgrp = warp & 7;
    const int dh   = warp >> 3;    // d-half: cols [dh*32, dh*32+32)
    const int r0 = rgrp * 32 + q;  // local rows r0,+8 (tileA) and +16,+24 (tileB)

    const float EsA0 = Es_s[r0],        EsA1 = Es_s[r0 + 8];
    const float EtA0 = Es02_s[r0],      EtA1 = Es02_s[r0 + 8];
    const float EsB0 = Es_s[r0 + 16],   EsB1 = Es_s[r0 + 24];
    const float EtB0 = Es02_s[r0 + 16], EtB1 = Es02_s[r0 + 24];

    float dA[4][4], dB[4][4];
    #pragma unroll
    for (int t = 0; t < 4; t++)
        #pragma unroll
        for (int j = 0; j < 4; j++) { dA[t][j] = 0.f; dB[t][j] = 0.f; }

    float sA0 = 0.f, sA1 = 0.f, sB0 = 0.f, sB1 = 0.f;
    const float* bbase = hpT + (dh * 32 + q) * HPT_S;

    #pragma unroll 2
    for (int k = 0; k < 64; k++) {
        const int m0 = k * 8 + 2 * c;   // k-permute: phys (c, c+4) -> m0, m0+1
        const float2 ed2 = *(const float2*)&Ed_s[m0];
        const float2 et2 = *(const float2*)&Ed02_s[m0];

        // A fragments: w = max(Es*Ed, Es02*Ed02)  (= exp(lrelu(es+ed)))
        float a0 = fmaxf(EsA0 * ed2.x, EtA0 * et2.x);
        float a1 = fmaxf(EsA1 * ed2.x, EtA1 * et2.x);
        float a2 = fmaxf(EsA0 * ed2.y, EtA0 * et2.y);
        float a3 = fmaxf(EsA1 * ed2.y, EtA1 * et2.y);
        float a4 = fmaxf(EsB0 * ed2.x, EtB0 * et2.x);
        float a5 = fmaxf(EsB1 * ed2.x, EtB1 * et2.x);
        float a6 = fmaxf(EsB0 * ed2.y, EtB0 * et2.y);
        float a7 = fmaxf(EsB1 * ed2.y, EtB1 * et2.y);
        sA0 += a0 + a2; sA1 += a1 + a3;
        sB0 += a4 + a6; sB1 += a5 + a7;

        #pragma unroll
        for (int j = 0; j < 4; j++) {
            const float2 b2 = *(const float2*)&bbase[j * 8 * HPT_S + m0];
            mma_tf32(dA[j], a0, a1, a2, a3, b2.x, b2.y);
            mma_tf32(dB[j], a4, a5, a6, a7, b2.x, b2.y);
        }
    }

    // Row sums: reduce over the 4 k-lanes (xor 1, 2)
    sA0 += __shfl_xor_sync(0xFFFFFFFFu, sA0, 1); sA0 += __shfl_xor_sync(0xFFFFFFFFu, sA0, 2);
    sA1 += __shfl_xor_sync(0xFFFFFFFFu, sA1, 1); sA1 += __shfl_xor_sync(0xFFFFFFFFu, sA1, 2);
    sB0 += __shfl_xor_sync(0xFFFFFFFFu, sB0, 1); sB0 += __shfl_xor_sync(0xFFFFFFFFu, sB0, 2);
    sB1 += __shfl_xor_sync(0xFFFFFFFFu, sB1, 1); sB1 += __shfl_xor_sync(0xFFFFFFFFu, sB1, 2);
    const float ivA0 = 1.f / sA0, ivA1 = 1.f / sA1;
    const float ivB0 = 1.f / sB0, ivB1 = 1.f / sB1;

    // Epilogue: normalize + ELU + store (this warp's 32 d-cols).
    const size_t orow = ((size_t)bh * NA + nbase + r0) * HD;
    float* o0 = out + orow;                 // row r0
    float* o1 = o0 + 8 * HD;                // r0+8
    float* o2 = o0 + 16 * HD;               // r0+16
    float* o3 = o0 + 24 * HD;               // r0+24
    #pragma unroll
    for (int j = 0; j < 4; j++) {
        const int dc = dh * 32 + j * 8 + 2 * c;
        float2 v;
        v.x = elu1(dA[j][0] * ivA0); v.y = elu1(dA[j][1] * ivA0);
        *(float2*)&o0[dc] = v;
        v.x = elu1(dA[j][2] * ivA1); v.y = elu1(dA[j][3] * ivA1);
        *(float2*)&o1[dc] = v;
        v.x = elu1(dB[j][0] * ivB0); v.y = elu1(dB[j][1] * ivB0);
        *(float2*)&o2[dc] = v;
        v.x = elu1(dB[j][2] * ivB1); v.y = elu1(dB[j][3] * ivB1);
        *(float2*)&o3[dc] = v;
    }
}

// ---------------------------------------------------------------------------
extern "C" void kernel_launch(void* const* d_in, const int* in_sizes, int n_in,
                              void* d_out, int out_size)
{
    const float* h     = (const float*)d_in[0];
    const float* W     = (const float*)d_in[1];
    const float* att_a = (const float*)d_in[2];
    float* out = (float*)d_out;

    cudaFuncSetAttribute(gemm_hp_tc,
        cudaFuncAttributeMaxDynamicSharedMemorySize, SMEM_G_BYTES);
    cudaFuncSetAttribute(attn_mma_kernel,
        cudaFuncAttributeMaxDynamicSharedMemorySize, SMEM_B_BYTES);

    gemm_hp_tc<<<BS * NH * 4, 256, SMEM_G_BYTES>>>(h, W);
    attn_mma_kernel<<<BS * NH * 2, 512, SMEM_B_BYTES>>>(att_a, out);
}

// round 7
// speedup vs baseline: 1.0701x; 1.0701x over previous
#include <cuda_runtime.h>
#include <math.h>
#include <stdint.h>

#define NEG_SLOPE 0.2f
#define LOG2E 1.4426950408889634f

// Problem constants
#define BS 32
#define NA 512          // n_agents
#define ID 128          // input_dim
#define NH 8            // n_heads
#define HD 64           // hidden_dim

// h_prime^T scratch: [b][head][d][m] = 32*8*64*512 floats = 33.5 MB
__device__ float g_hpT[BS * NH * HD * NA];

// ---------------------------------------------------------------------------
// helpers
// ---------------------------------------------------------------------------
__device__ __forceinline__ float to_tf32(float x) {
    uint32_t u;
    asm("cvt.rn.tf32.f32 %0, %1;" : "=r"(u) : "f"(x));
    return __uint_as_float(u);
}
__device__ __forceinline__ float ex2(float x) {
    float r;
    asm("ex2.approx.f32 %0, %1;" : "=f"(r) : "f"(x));
    return r;
}
__device__ __forceinline__ void mma_tf32(float d[4], float a0, float a1,
                                         float a2, float a3, float b0, float b1) {
    asm volatile(
        "mma.sync.aligned.m16n8k8.row.col.f32.tf32.tf32.f32 "
        "{%0,%1,%2,%3}, {%4,%5,%6,%7}, {%8,%9}, {%0,%1,%2,%3};"
        : "+f"(d[0]), "+f"(d[1]), "+f"(d[2]), "+f"(d[3])
        : "r"(__float_as_uint(a0)), "r"(__float_as_uint(a1)),
          "r"(__float_as_uint(a2)), "r"(__float_as_uint(a3)),
          "r"(__float_as_uint(b0)), "r"(__float_as_uint(b1)));
}

// ---------------------------------------------------------------------------
// Kernel A: g_hpT = Wt @ h^T via split-tf32 mma, k-chunked staging so 2 CTAs
// fit per SM (102KB smem each). CTA = (b, head, n-quarter). 256 thr, 8 warps.
// ---------------------------------------------------------------------------
#define KC 64
#define KC_S 68
#define SMEM_G_BYTES ((2 * 64 * KC_S + 2 * 128 * KC_S) * 4)   // 104448

__global__ void __launch_bounds__(256, 2) gemm_hp_tc(
    const float* __restrict__ h, const float* __restrict__ W)
{
    extern __shared__ float smg[];
    float* Wt_hi = smg;                    // [64][KC_S]
    float* Wt_lo = Wt_hi + 64 * KC_S;
    float* h_hi  = Wt_lo + 64 * KC_S;      // [128][KC_S]
    float* h_lo  = h_hi + 128 * KC_S;

    const int tid = threadIdx.x;
    const int bxx = blockIdx.x;
    const int b    = bxx >> 5;
    const int head = (bxx >> 2) & 7;
    const int nq   = bxx & 3;
    const int n0   = nq * 128;
    const int col0 = head * HD;

    const int warp = tid >> 5;
    const int lane = tid & 31;
    const int q = lane >> 2;
    const int c = lane & 3;
    const int mt = warp >> 1;    // d-tile (0..3): rows mt*16 + {q, q+8}
    const int nh = warp & 1;     // n-half (0..1): 8 n8-fragments

    float acc[8][4];
    #pragma unroll
    for (int f = 0; f < 8; f++)
        #pragma unroll
        for (int j = 0; j < 4; j++) acc[f][j] = 0.f;

    const float* wa_hi = Wt_hi + (mt * 16 + q) * KC_S + 2 * c;
    const float* wa_lo = Wt_lo + (mt * 16 + q) * KC_S + 2 * c;
    const float* hb_hi = h_hi + (nh * 64 + q) * KC_S + 2 * c;
    const float* hb_lo = h_lo + (nh * 64 + q) * KC_S + 2 * c;

    for (int kc = 0; kc < 2; kc++) {
        if (kc) __syncthreads();   // protect smem reuse

        // Stage W^T chunk (hi/lo): 64 d x 64 k
        #pragma unroll 4
        for (int i = 0; i < 16; i++) {
            int t = tid + i * 256;
            int d = t & 63, k = t >> 6;
            float v = W[(size_t)(kc * KC + k) * 512 + col0 + d];
            float hi = to_tf32(v);
            Wt_hi[d * KC_S + k] = hi;
            Wt_lo[d * KC_S + k] = to_tf32(v - hi);
        }
        // Stage h chunk (hi/lo): 128 n x 64 k
        #pragma unroll 4
        for (int i = 0; i < 8; i++) {
            int t = tid + i * 256;
            int n = t >> 4, kq = t & 15;
            float4 v = *(const float4*)&h[((size_t)(b * NA + n0 + n)) * ID + kc * KC + kq * 4];
            float4 hi4, lo4;
            hi4.x = to_tf32(v.x); lo4.x = to_tf32(v.x - hi4.x);
            hi4.y = to_tf32(v.y); lo4.y = to_tf32(v.y - hi4.y);
            hi4.z = to_tf32(v.z); lo4.z = to_tf32(v.z - hi4.z);
            hi4.w = to_tf32(v.w); lo4.w = to_tf32(v.w - hi4.w);
            *(float4*)&h_hi[n * KC_S + kq * 4] = hi4;
            *(float4*)&h_lo[n * KC_S + kq * 4] = lo4;
        }
        __syncthreads();

        #pragma unroll 2
        for (int k8 = 0; k8 < 8; k8++) {
            const int ko = k8 * 8;
            float2 ah0 = *(const float2*)&wa_hi[ko];
            float2 ah1 = *(const float2*)&wa_hi[8 * KC_S + ko];
            float2 al0 = *(const float2*)&wa_lo[ko];
            float2 al1 = *(const float2*)&wa_lo[8 * KC_S + ko];
            #pragma unroll
            for (int nf = 0; nf < 8; nf++) {
                float2 bh = *(const float2*)&hb_hi[nf * 8 * KC_S + ko];
                float2 bl = *(const float2*)&hb_lo[nf * 8 * KC_S + ko];
                mma_tf32(acc[nf], ah0.x, ah1.x, ah0.y, ah1.y, bh.x, bh.y); // hi*hi
                mma_tf32(acc[nf], al0.x, al1.x, al0.y, al1.y, bh.x, bh.y); // lo*hi
                mma_tf32(acc[nf], ah0.x, ah1.x, ah0.y, ah1.y, bl.x, bl.y); // hi*lo
            }
        }
    }

    // Epilogue: D[d][n] -> g_hpT rows dg, dg+8
    const int dg = mt * 16 + q;
    float* og = g_hpT + ((size_t)(b * NH + head) * HD + dg) * NA + n0 + nh * 64 + 2 * c;
    #pragma unroll
    for (int nf = 0; nf < 8; nf++) {
        *(float2*)&og[nf * 8]          = make_float2(acc[nf][0], acc[nf][1]);
        *(float2*)&og[8 * NA + nf * 8] = make_float2(acc[nf][2], acc[nf][3]);
    }
}

// ---------------------------------------------------------------------------
// Kernel B: mma.sync tf32 attention (R5 shape: 256 thr, 8 warps, 2 CTAs/bh)
// with explicit k+1 software pipelining of e-scores and B fragments.
// ---------------------------------------------------------------------------
#define HPT_S 516
#define SM_HPT   0
#define SM_ED    (64 * HPT_S)            // [512]  (bbase/Ed overreads land in-bounds)
#define SM_ED02  (SM_ED + 512)           // [512]
#define SM_ES    (SM_ED02 + 512)         // [256]
#define SM_ES02  (SM_ES + 256)           // [256]
#define SM_A     (SM_ES02 + 256)         // [128]
#define SMEM_B_FLOATS (SM_A + 128 + 8)
#define SMEM_B_BYTES (SMEM_B_FLOATS * 4)

__device__ __forceinline__ float elu1(float x) {
    return x > 0.f ? x : expm1f(x);
}

__global__ void __launch_bounds__(256, 1) attn_mma_kernel(
    const float* __restrict__ att_a, float* __restrict__ out)
{
    extern __shared__ float sm[];
    float* hpT    = sm + SM_HPT;
    float* Ed_s   = sm + SM_ED;
    float* Ed02_s = sm + SM_ED02;
    float* Es_s   = sm + SM_ES;
    float* Es02_s = sm + SM_ES02;
    float* a_s    = sm + SM_A;

    const int bx = blockIdx.x;
    const int bh = bx >> 1;
    const int head = bh & 7;
    const int nbase = (bx & 1) * 256;
    const int tid = threadIdx.x;
    const int warp = tid >> 5;
    const int lane = tid & 31;
    const int q = lane >> 2;       // group id (rows / B n-col)
    const int c = lane & 3;        // k position / D col pair

    if (tid < 128) a_s[tid] = att_a[head * 128 + tid];

    // Stage hpT (tf32-rounded) into padded SMEM
    const float* hg = g_hpT + (size_t)bh * HD * NA;
    #pragma unroll 4
    for (int i = 0; i < 32; i++) {
        int f = tid + i * 256;           // 8192 float4s
        int d = f >> 7;
        int mq = f & 127;
        float4 v = *(const float4*)&hg[(size_t)d * NA + mq * 4];
        v.x = to_tf32(v.x); v.y = to_tf32(v.y);
        v.z = to_tf32(v.z); v.w = to_tf32(v.w);
        *(float4*)&hpT[d * HPT_S + mq * 4] = v;
    }
    __syncthreads();

    // e-scores from rounded hp: Ed for all m, Es for this CTA's 256 rows.
    for (int m = tid; m < NA; m += 256) {
        float es = 0.f, ed = 0.f;
        #pragma unroll
        for (int d = 0; d < 64; d++) {
            float hp = hpT[d * HPT_S + m];
            es += hp * a_s[d];
            ed += hp * a_s[64 + d];
        }
        Ed_s[m]   = ex2(ed * LOG2E);
        Ed02_s[m] = ex2(ed * (NEG_SLOPE * LOG2E));
        int r = m - nbase;
        if ((unsigned)r < 256u) {
            Es_s[r]   = ex2(es * LOG2E);
            Es02_s[r] = ex2(es * (NEG_SLOPE * LOG2E));
        }
    }
    __syncthreads();

    // Warp owns local rows [warp*32, warp*32+32): two m16 tiles.
    const int r0 = warp * 32 + q;
    const float EsA0 = Es_s[r0],        EsA1 = Es_s[r0 + 8];
    const float EtA0 = Es02_s[r0],      EtA1 = Es02_s[r0 + 8];
    const float EsB0 = Es_s[r0 + 16],   EsB1 = Es_s[r0 + 24];
    const float EtB0 = Es02_s[r0 + 16], EtB1 = Es02_s[r0 + 24];

    float dA[8][4], dB[8][4];
    #pragma unroll
    for (int t = 0; t < 8; t++)
        #pragma unroll
        for (int j = 0; j < 4; j++) { dA[t][j] = 0.f; dB[t][j] = 0.f; }

    float sA0 = 0.f, sA1 = 0.f, sB0 = 0.f, sB1 = 0.f;
    const float* bbase = hpT + q * HPT_S;

    // ---- software-pipelined k-loop: prefetch k+1's e and B frags ----
    float2 ed_c = *(const float2*)&Ed_s[2 * c];
    float2 et_c = *(const float2*)&Ed02_s[2 * c];
    float2 bc[8];
    #pragma unroll
    for (int j = 0; j < 8; j++)
        bc[j] = *(const float2*)&bbase[j * 8 * HPT_S + 2 * c];

    #pragma unroll 2
    for (int k = 0; k < 64; k++) {
        const int mn = k * 8 + 8 + 2 * c;  // next iter (k=63 overreads safely in smem)
        float2 ed_n = *(const float2*)&Ed_s[mn];
        float2 et_n = *(const float2*)&Ed02_s[mn];
        float2 bn[8];
        #pragma unroll
        for (int j = 0; j < 8; j++)
            bn[j] = *(const float2*)&bbase[j * 8 * HPT_S + mn];

        // A fragments: w = max(Es*Ed, Es02*Ed02) = exp(lrelu(es+ed))
        float a0 = fmaxf(EsA0 * ed_c.x, EtA0 * et_c.x);
        float a1 = fmaxf(EsA1 * ed_c.x, EtA1 * et_c.x);
        float a2 = fmaxf(EsA0 * ed_c.y, EtA0 * et_c.y);
        float a3 = fmaxf(EsA1 * ed_c.y, EtA1 * et_c.y);
        float a4 = fmaxf(EsB0 * ed_c.x, EtB0 * et_c.x);
        float a5 = fmaxf(EsB1 * ed_c.x, EtB1 * et_c.x);
        float a6 = fmaxf(EsB0 * ed_c.y, EtB0 * et_c.y);
        float a7 = fmaxf(EsB1 * ed_c.y, EtB1 * et_c.y);
        sA0 += a0 + a2; sA1 += a1 + a3;
        sB0 += a4 + a6; sB1 += a5 + a7;

        #pragma unroll
        for (int j = 0; j < 8; j++) {
            mma_tf32(dA[j], a0, a1, a2, a3, bc[j].x, bc[j].y);
            mma_tf32(dB[j], a4, a5, a6, a7, bc[j].x, bc[j].y);
        }

        ed_c = ed_n; et_c = et_n;
        #pragma unroll
        for (int j = 0; j < 8; j++) bc[j] = bn[j];
    }

    // Row sums: reduce over the 4 k-lanes
    sA0 += __shfl_xor_sync(0xFFFFFFFFu, sA0, 1); sA0 += __shfl_xor_sync(0xFFFFFFFFu, sA0, 2);
    sA1 += __shfl_xor_sync(0xFFFFFFFFu, sA1, 1); sA1 += __shfl_xor_sync(0xFFFFFFFFu, sA1, 2);
    sB0 += __shfl_xor_sync(0xFFFFFFFFu, sB0, 1); sB0 += __shfl_xor_sync(0xFFFFFFFFu, sB0, 2);
    sB1 += __shfl_xor_sync(0xFFFFFFFFu, sB1, 1); sB1 += __shfl_xor_sync(0xFFFFFFFFu, sB1, 2);
    const float ivA0 = 1.f / sA0, ivA1 = 1.f / sA1;
    const float ivB0 = 1.f / sB0, ivB1 = 1.f / sB1;

    // Epilogue: normalize + ELU + store.
    const size_t orow = ((size_t)bh * NA + nbase + r0) * HD;
    float* o0 = out + orow;                 // row r0
    float* o1 = o0 + 8 * HD;                // r0+8
    float* o2 = o0 + 16 * HD;               // r0+16
    float* o3 = o0 + 24 * HD;               // r0+24
    #pragma unroll
    for (int dt = 0; dt < 8; dt++) {
        const int dc = dt * 8 + 2 * c;
        float2 v;
        v.x = elu1(dA[dt][0] * ivA0); v.y = elu1(dA[dt][1] * ivA0);
        *(float2*)&o0[dc] = v;
        v.x = elu1(dA[dt][2] * ivA1); v.y = elu1(dA[dt][3] * ivA1);
        *(float2*)&o1[dc] = v;
        v.x = elu1(dB[dt][0] * ivB0); v.y = elu1(dB[dt][1] * ivB0);
        *(float2*)&o2[dc] = v;
        v.x = elu1(dB[dt][2] * ivB1); v.y = elu1(dB[dt][3] * ivB1);
        *(float2*)&o3[dc] = v;
    }
}

// ---------------------------------------------------------------------------
extern "C" void kernel_launch(void* const* d_in, const int* in_sizes, int n_in,
                              void* d_out, int out_size)
{
    const float* h     = (const float*)d_in[0];
    const float* W     = (const float*)d_in[1];
    const float* att_a = (const float*)d_in[2];
    float* out = (float*)d_out;

    cudaFuncSetAttribute(gemm_hp_tc,
        cudaFuncAttributeMaxDynamicSharedMemorySize, SMEM_G_BYTES);
    cudaFuncSetAttribute(attn_mma_kernel,
        cudaFuncAttributeMaxDynamicSharedMemorySize, SMEM_B_BYTES);

    gemm_hp_tc<<<BS * NH * 4, 256, SMEM_G_BYTES>>>(h, W);
    attn_mma_kernel<<<BS * NH * 2, 256, SMEM_B_BYTES>>>(att_a, out);
}

// round 8
// speedup vs baseline: 1.0924x; 1.0208x over previous
#include <cuda_runtime.h>
#include <math.h>
#include <stdint.h>

#define NEG_SLOPE 0.2f
#define LOG2E 1.4426950408889634f

// Problem constants
#define BS 32
#define NA 512          // n_agents
#define ID 128          // input_dim
#define NH 8            // n_heads
#define HD 64           // hidden_dim

// h_prime^T scratch: [b][head][d][m] = 32*8*64*512 floats = 33.5 MB
__device__ float g_hpT[BS * NH * HD * NA];

// ---------------------------------------------------------------------------
// helpers
// ---------------------------------------------------------------------------
__device__ __forceinline__ float to_tf32(float x) {
    uint32_t u;
    asm("cvt.rn.tf32.f32 %0, %1;" : "=r"(u) : "f"(x));
    return __uint_as_float(u);
}
__device__ __forceinline__ float ex2(float x) {
    float r;
    asm("ex2.approx.f32 %0, %1;" : "=f"(r) : "f"(x));
    return r;
}
__device__ __forceinline__ void mma_tf32(float d[4], float a0, float a1,
                                         float a2, float a3, float b0, float b1) {
    asm volatile(
        "mma.sync.aligned.m16n8k8.row.col.f32.tf32.tf32.f32 "
        "{%0,%1,%2,%3}, {%4,%5,%6,%7}, {%8,%9}, {%0,%1,%2,%3};"
        : "+f"(d[0]), "+f"(d[1]), "+f"(d[2]), "+f"(d[3])
        : "r"(__float_as_uint(a0)), "r"(__float_as_uint(a1)),
          "r"(__float_as_uint(a2)), "r"(__float_as_uint(a3)),
          "r"(__float_as_uint(b0)), "r"(__float_as_uint(b1)));
}

// ---------------------------------------------------------------------------
// Kernel A: g_hpT = Wt @ h^T via split-tf32 mma, k-chunked staging so 2 CTAs
// fit per SM. (unchanged from R7)
// ---------------------------------------------------------------------------
#define KC 64
#define KC_S 68
#define SMEM_G_BYTES ((2 * 64 * KC_S + 2 * 128 * KC_S) * 4)   // 104448

__global__ void __launch_bounds__(256, 2) gemm_hp_tc(
    const float* __restrict__ h, const float* __restrict__ W)
{
    extern __shared__ float smg[];
    float* Wt_hi = smg;                    // [64][KC_S]
    float* Wt_lo = Wt_hi + 64 * KC_S;
    float* h_hi  = Wt_lo + 64 * KC_S;      // [128][KC_S]
    float* h_lo  = h_hi + 128 * KC_S;

    const int tid = threadIdx.x;
    const int bxx = blockIdx.x;
    const int b    = bxx >> 5;
    const int head = (bxx >> 2) & 7;
    const int nq   = bxx & 3;
    const int n0   = nq * 128;
    const int col0 = head * HD;

    const int warp = tid >> 5;
    const int lane = tid & 31;
    const int q = lane >> 2;
    const int c = lane & 3;
    const int mt = warp >> 1;
    const int nh = warp & 1;

    float acc[8][4];
    #pragma unroll
    for (int f = 0; f < 8; f++)
        #pragma unroll
        for (int j = 0; j < 4; j++) acc[f][j] = 0.f;

    const float* wa_hi = Wt_hi + (mt * 16 + q) * KC_S + 2 * c;
    const float* wa_lo = Wt_lo + (mt * 16 + q) * KC_S + 2 * c;
    const float* hb_hi = h_hi + (nh * 64 + q) * KC_S + 2 * c;
    const float* hb_lo = h_lo + (nh * 64 + q) * KC_S + 2 * c;

    for (int kc = 0; kc < 2; kc++) {
        if (kc) __syncthreads();

        #pragma unroll 4
        for (int i = 0; i < 16; i++) {
            int t = tid + i * 256;
            int d = t & 63, k = t >> 6;
            float v = W[(size_t)(kc * KC + k) * 512 + col0 + d];
            float hi = to_tf32(v);
            Wt_hi[d * KC_S + k] = hi;
            Wt_lo[d * KC_S + k] = to_tf32(v - hi);
        }
        #pragma unroll 4
        for (int i = 0; i < 8; i++) {
            int t = tid + i * 256;
            int n = t >> 4, kq = t & 15;
            float4 v = *(const float4*)&h[((size_t)(b * NA + n0 + n)) * ID + kc * KC + kq * 4];
            float4 hi4, lo4;
            hi4.x = to_tf32(v.x); lo4.x = to_tf32(v.x - hi4.x);
            hi4.y = to_tf32(v.y); lo4.y = to_tf32(v.y - hi4.y);
            hi4.z = to_tf32(v.z); lo4.z = to_tf32(v.z - hi4.z);
            hi4.w = to_tf32(v.w); lo4.w = to_tf32(v.w - hi4.w);
            *(float4*)&h_hi[n * KC_S + kq * 4] = hi4;
            *(float4*)&h_lo[n * KC_S + kq * 4] = lo4;
        }
        __syncthreads();

        #pragma unroll 2
        for (int k8 = 0; k8 < 8; k8++) {
            const int ko = k8 * 8;
            float2 ah0 = *(const float2*)&wa_hi[ko];
            float2 ah1 = *(const float2*)&wa_hi[8 * KC_S + ko];
            float2 al0 = *(const float2*)&wa_lo[ko];
            float2 al1 = *(const float2*)&wa_lo[8 * KC_S + ko];
            #pragma unroll
            for (int nf = 0; nf < 8; nf++) {
                float2 bh = *(const float2*)&hb_hi[nf * 8 * KC_S + ko];
                float2 bl = *(const float2*)&hb_lo[nf * 8 * KC_S + ko];
                mma_tf32(acc[nf], ah0.x, ah1.x, ah0.y, ah1.y, bh.x, bh.y);
                mma_tf32(acc[nf], al0.x, al1.x, al0.y, al1.y, bh.x, bh.y);
                mma_tf32(acc[nf], ah0.x, ah1.x, ah0.y, ah1.y, bl.x, bl.y);
            }
        }
    }

    const int dg = mt * 16 + q;
    float* og = g_hpT + ((size_t)(b * NH + head) * HD + dg) * NA + n0 + nh * 64 + 2 * c;
    #pragma unroll
    for (int nf = 0; nf < 8; nf++) {
        *(float2*)&og[nf * 8]          = make_float2(acc[nf][0], acc[nf][1]);
        *(float2*)&og[8 * NA + nf * 8] = make_float2(acc[nf][2], acc[nf][3]);
    }
}

// ---------------------------------------------------------------------------
// Kernel B: mma.sync tf32 attention, 512 threads = 8 rowgroups x 2 m-halves.
// Each warp runs the R5 inner loop over its m-half (32 k8 iters). After the
// k-loop, hpT SMEM is dead and is reused as cross-warp reduction scratch.
// ---------------------------------------------------------------------------
#define HPT_S 516
#define SM_HPT   0
#define SM_ED    (64 * HPT_S)            // [512]
#define SM_ED02  (SM_ED + 512)           // [512]
#define SM_ES    (SM_ED02 + 512)         // [256]
#define SM_ES02  (SM_ES + 256)           // [256]
#define SM_A     (SM_ES02 + 256)         // [128]
#define SMEM_B_FLOATS (SM_A + 128 + 8)
#define SMEM_B_BYTES (SMEM_B_FLOATS * 4)
#define SCR_STRIDE 69                    // de-banked scratch stride

__device__ __forceinline__ float elu1(float x) {
    return x > 0.f ? x : expm1f(x);
}

__global__ void __launch_bounds__(512, 1) attn_mma_kernel(
    const float* __restrict__ att_a, float* __restrict__ out)
{
    extern __shared__ float sm[];
    float* hpT    = sm + SM_HPT;
    float* Ed_s   = sm + SM_ED;
    float* Ed02_s = sm + SM_ED02;
    float* Es_s   = sm + SM_ES;
    float* Es02_s = sm + SM_ES02;
    float* a_s    = sm + SM_A;

    const int bx = blockIdx.x;
    const int bh = bx >> 1;
    const int head = bh & 7;
    const int nbase = (bx & 1) * 256;
    const int tid = threadIdx.x;
    const int warp = tid >> 5;
    const int lane = tid & 31;
    const int q = lane >> 2;       // group id (rows / B n-col)
    const int c = lane & 3;        // k position / D col pair
    const int rgrp = warp & 7;     // row group (32 rows)
    const int mh = warp >> 3;      // m-half (0/1)

    if (tid < 128) a_s[tid] = att_a[head * 128 + tid];

    // Stage hpT (tf32-rounded) into padded SMEM
    const float* hg = g_hpT + (size_t)bh * HD * NA;
    #pragma unroll 4
    for (int i = 0; i < 16; i++) {
        int f = tid + i * 512;           // 8192 float4s
        int d = f >> 7;
        int mq = f & 127;
        float4 v = *(const float4*)&hg[(size_t)d * NA + mq * 4];
        v.x = to_tf32(v.x); v.y = to_tf32(v.y);
        v.z = to_tf32(v.z); v.w = to_tf32(v.w);
        *(float4*)&hpT[d * HPT_S + mq * 4] = v;
    }
    __syncthreads();

    // e-scores: one m per thread
    {
        const int m = tid;
        float es = 0.f, ed = 0.f;
        #pragma unroll
        for (int d = 0; d < 64; d++) {
            float hp = hpT[d * HPT_S + m];
            es += hp * a_s[d];
            ed += hp * a_s[64 + d];
        }
        Ed_s[m]   = ex2(ed * LOG2E);
        Ed02_s[m] = ex2(ed * (NEG_SLOPE * LOG2E));
        int r = m - nbase;
        if ((unsigned)r < 256u) {
            Es_s[r]   = ex2(es * LOG2E);
            Es02_s[r] = ex2(es * (NEG_SLOPE * LOG2E));
        }
    }
    __syncthreads();

    // Warp owns local rows [rgrp*32, rgrp*32+32) over m-half mh.
    const int r0 = rgrp * 32 + q;
    const float EsA0 = Es_s[r0],        EsA1 = Es_s[r0 + 8];
    const float EtA0 = Es02_s[r0],      EtA1 = Es02_s[r0 + 8];
    const float EsB0 = Es_s[r0 + 16],   EsB1 = Es_s[r0 + 24];
    const float EtB0 = Es02_s[r0 + 16], EtB1 = Es02_s[r0 + 24];

    float dA[8][4], dB[8][4];
    #pragma unroll
    for (int t = 0; t < 8; t++)
        #pragma unroll
        for (int j = 0; j < 4; j++) { dA[t][j] = 0.f; dB[t][j] = 0.f; }

    float sA0 = 0.f, sA1 = 0.f, sB0 = 0.f, sB1 = 0.f;
    const float* bbase = hpT + q * HPT_S;
    const int m_off = mh * 256;

    #pragma unroll 2
    for (int k = 0; k < 32; k++) {
        const int m0 = m_off + k * 8 + 2 * c;
        const float2 ed2 = *(const float2*)&Ed_s[m0];
        const float2 et2 = *(const float2*)&Ed02_s[m0];

        // A fragments: w = max(Es*Ed, Es02*Ed02) = exp(lrelu(es+ed))
        float a0 = fmaxf(EsA0 * ed2.x, EtA0 * et2.x);
        float a1 = fmaxf(EsA1 * ed2.x, EtA1 * et2.x);
        float a2 = fmaxf(EsA0 * ed2.y, EtA0 * et2.y);
        float a3 = fmaxf(EsA1 * ed2.y, EtA1 * et2.y);
        float a4 = fmaxf(EsB0 * ed2.x, EtB0 * et2.x);
        float a5 = fmaxf(EsB1 * ed2.x, EtB1 * et2.x);
        float a6 = fmaxf(EsB0 * ed2.y, EtB0 * et2.y);
        float a7 = fmaxf(EsB1 * ed2.y, EtB1 * et2.y);
        sA0 += a0 + a2; sA1 += a1 + a3;
        sB0 += a4 + a6; sB1 += a5 + a7;

        #pragma unroll
        for (int dt = 0; dt < 8; dt++) {
            const float2 b2 = *(const float2*)&bbase[dt * 8 * HPT_S + m0];
            mma_tf32(dA[dt], a0, a1, a2, a3, b2.x, b2.y);
            mma_tf32(dB[dt], a4, a5, a6, a7, b2.x, b2.y);
        }
    }

    // Partial row sums within this warp (over its 4 k-lanes)
    sA0 += __shfl_xor_sync(0xFFFFFFFFu, sA0, 1); sA0 += __shfl_xor_sync(0xFFFFFFFFu, sA0, 2);
    sA1 += __shfl_xor_sync(0xFFFFFFFFu, sA1, 1); sA1 += __shfl_xor_sync(0xFFFFFFFFu, sA1, 2);
    sB0 += __shfl_xor_sync(0xFFFFFFFFu, sB0, 1); sB0 += __shfl_xor_sync(0xFFFFFFFFu, sB0, 2);
    sB1 += __shfl_xor_sync(0xFFFFFFFFu, sB1, 1); sB1 += __shfl_xor_sync(0xFFFFFFFFu, sB1, 2);

    // ---- cross m-half combine: hpT region is dead, reuse as scratch ----
    __syncthreads();
    float* scr = hpT + (rgrp * 32 + lane) * SCR_STRIDE;
    if (mh == 1) {
        #pragma unroll
        for (int dt = 0; dt < 8; dt++) {
            #pragma unroll
            for (int j = 0; j < 4; j++) {
                scr[dt * 4 + j]      = dA[dt][j];
                scr[32 + dt * 4 + j] = dB[dt][j];
            }
        }
        scr[64] = sA0; scr[65] = sA1; scr[66] = sB0; scr[67] = sB1;
    }
    __syncthreads();

    if (mh == 0) {
        #pragma unroll
        for (int dt = 0; dt < 8; dt++) {
            #pragma unroll
            for (int j = 0; j < 4; j++) {
                dA[dt][j] += scr[dt * 4 + j];
                dB[dt][j] += scr[32 + dt * 4 + j];
            }
        }
        sA0 += scr[64]; sA1 += scr[65]; sB0 += scr[66]; sB1 += scr[67];

        const float ivA0 = 1.f / sA0, ivA1 = 1.f / sA1;
        const float ivB0 = 1.f / sB0, ivB1 = 1.f / sB1;

        // Epilogue: normalize + ELU + store.
        const size_t orow = ((size_t)bh * NA + nbase + r0) * HD;
        float* o0 = out + orow;                 // row r0
        float* o1 = o0 + 8 * HD;                // r0+8
        float* o2 = o0 + 16 * HD;               // r0+16
        float* o3 = o0 + 24 * HD;               // r0+24
        #pragma unroll
        for (int dt = 0; dt < 8; dt++) {
            const int dc = dt * 8 + 2 * c;
            float2 v;
            v.x = elu1(dA[dt][0] * ivA0); v.y = elu1(dA[dt][1] * ivA0);
            *(float2*)&o0[dc] = v;
            v.x = elu1(dA[dt][2] * ivA1); v.y = elu1(dA[dt][3] * ivA1);
            *(float2*)&o1[dc] = v;
            v.x = elu1(dB[dt][0] * ivB0); v.y = elu1(dB[dt][1] * ivB0);
            *(float2*)&o2[dc] = v;
            v.x = elu1(dB[dt][2] * ivB1); v.y = elu1(dB[dt][3] * ivB1);
            *(float2*)&o3[dc] = v;
        }
    }
}

// ---------------------------------------------------------------------------
extern "C" void kernel_launch(void* const* d_in, const int* in_sizes, int n_in,
                              void* d_out, int out_size)
{
    const float* h     = (const float*)d_in[0];
    const float* W     = (const float*)d_in[1];
    const float* att_a = (const float*)d_in[2];
    float* out = (float*)d_out;

    cudaFuncSetAttribute(gemm_hp_tc,
        cudaFuncAttributeMaxDynamicSharedMemorySize, SMEM_G_BYTES);
    cudaFuncSetAttribute(attn_mma_kernel,
        cudaFuncAttributeMaxDynamicSharedMemorySize, SMEM_B_BYTES);

    gemm_hp_tc<<<BS * NH * 4, 256, SMEM_G_BYTES>>>(h, W);
    attn_mma_kernel<<<BS * NH * 2, 512, SMEM_B_BYTES>>>(att_a, out);
}

// round 9
// speedup vs baseline: 1.2200x; 1.1168x over previous
#include <cuda_runtime.h>
#include <math.h>
#include <stdint.h>

#define NEG_SLOPE 0.2f
#define LOG2E 1.4426950408889634f

// Problem constants
#define BS 32
#define NA 512          // n_agents
#define ID 128          // input_dim
#define NH 8            // n_heads
#define HD 64           // hidden_dim

// ---------------------------------------------------------------------------
// helpers
// ---------------------------------------------------------------------------
__device__ __forceinline__ float to_tf32(float x) {
    uint32_t u;
    asm("cvt.rn.tf32.f32 %0, %1;" : "=r"(u) : "f"(x));
    return __uint_as_float(u);
}
__device__ __forceinline__ float ex2(float x) {
    float r;
    asm("ex2.approx.f32 %0, %1;" : "=f"(r) : "f"(x));
    return r;
}
__device__ __forceinline__ void mma_tf32(float d[4], float a0, float a1,
                                         float a2, float a3, float b0, float b1) {
    asm volatile(
        "mma.sync.aligned.m16n8k8.row.col.f32.tf32.tf32.f32 "
        "{%0,%1,%2,%3}, {%4,%5,%6,%7}, {%8,%9}, {%0,%1,%2,%3};"
        : "+f"(d[0]), "+f"(d[1]), "+f"(d[2]), "+f"(d[3])
        : "r"(__float_as_uint(a0)), "r"(__float_as_uint(a1)),
          "r"(__float_as_uint(a2)), "r"(__float_as_uint(a3)),
          "r"(__float_as_uint(b0)), "r"(__float_as_uint(b1)));
}
__device__ __forceinline__ float elu1(float x) {
    return x > 0.f ? x : expm1f(x);
}

// ---------------------------------------------------------------------------
// Fused kernel: one CTA per (b, head). 512 threads = 16 warps.
//
// Phase 1 (GEMM): hpT[64 d][512 m] = W^T @ h^T via split-tf32 mma
//   (3 products: hi*hi + lo*hi + hi*lo), 8 k-chunks of 16. h staged raw fp32,
//   hi/lo extracted in registers. Result stored tf32-rounded into SMEM.
// Phase 1.5: e-scores from hpT (one m per thread), stored as exp factors.
// Phase 2 (attention): warp = (row-half, rowgroup) -> 32 rows x full 512-m
//   scan. A-frags generated as w = max(Es*Ed, Es02*Ed02); B-frags = LDS.64
//   from hpT; row sums in registers -> folded into epilogue with ELU.
// ---------------------------------------------------------------------------
#define HPT_S 516
#define HS 24               // h_s stride (bank-conflict-free B-frag loads)
#define WS 18               // W stage stride
#define KC 16               // k-chunk

#define SM_HPT   0
#define SM_HSTG  (64 * HPT_S)              // h_s [512][24]
#define SM_WH    (SM_HSTG + 512 * HS)      // Wh [64][18]
#define SM_WL    (SM_WH + 64 * WS)         // Wl [64][18]
#define SM_ED    (SM_WL + 64 * WS)         // [512]
#define SM_ED02  (SM_ED + 512)             // [512]
#define SM_ES    (SM_ED02 + 512)           // [512]
#define SM_ES02  (SM_ES + 512)             // [512]
#define SM_A     (SM_ES02 + 512)           // [128]
#define SMEM_F_FLOATS (SM_A + 128 + 8)
#define SMEM_F_BYTES (SMEM_F_FLOATS * 4)   // ~199.4 KB

__global__ void __launch_bounds__(512, 1) gat_fused_kernel(
    const float* __restrict__ h, const float* __restrict__ W,
    const float* __restrict__ att_a, float* __restrict__ out)
{
    extern __shared__ float sm[];
    float* hpT    = sm + SM_HPT;
    float* h_s    = sm + SM_HSTG;
    float* Wh     = sm + SM_WH;
    float* Wl     = sm + SM_WL;
    float* Ed_s   = sm + SM_ED;
    float* Ed02_s = sm + SM_ED02;
    float* Es_s   = sm + SM_ES;
    float* Es02_s = sm + SM_ES02;
    float* a_s    = sm + SM_A;

    const int bh = blockIdx.x;
    const int head = bh & 7;
    const int b = bh >> 3;
    const int col0 = head * HD;
    const int tid = threadIdx.x;
    const int warp = tid >> 5;
    const int lane = tid & 31;
    const int q = lane >> 2;       // group id
    const int c = lane & 3;        // k position / col pair

    if (tid < 128) a_s[tid] = att_a[head * 128 + tid];

    // ======================= Phase 1: GEMM -> hpT =======================
    const int dt = warp & 3;       // d-tile: rows dt*16 + {q, q+8}
    const int mq = warp >> 2;      // m-quarter: cols mq*128 + nf*8

    float acc[16][4];
    #pragma unroll
    for (int f = 0; f < 16; f++)
        #pragma unroll
        for (int j = 0; j < 4; j++) acc[f][j] = 0.f;

    const float* hrow = h + ((size_t)(b * NA) + tid) * ID;
    const float* wa_h = Wh + (dt * 16 + q) * WS + 2 * c;
    const float* wa_l = Wl + (dt * 16 + q) * WS + 2 * c;
    const float* hb   = h_s + (mq * 128 + q) * HS + 2 * c;

    for (int kc = 0; kc < 8; kc++) {
        if (kc) __syncthreads();   // protect h_s/W reuse

        // Stage W^T chunk (hi/lo): 64 d x 16 k
        #pragma unroll
        for (int i = 0; i < 2; i++) {
            int t = tid + i * 512;
            int d = t & 63, k = t >> 6;
            float v = W[(size_t)(kc * KC + k) * 512 + col0 + d];
            float hi = to_tf32(v);
            Wh[d * WS + k] = hi;
            Wl[d * WS + k] = to_tf32(v - hi);
        }
        // Stage h chunk raw fp32: row tid, 16 k
        #pragma unroll
        for (int i = 0; i < 4; i++) {
            float4 v = *(const float4*)&hrow[kc * KC + i * 4];
            *(float4*)&h_s[tid * HS + i * 4] = v;
        }
        __syncthreads();

        #pragma unroll
        for (int ks = 0; ks < 2; ks++) {
            const int ko = ks * 8;
            float2 ah0 = *(const float2*)&wa_h[ko];            // row q
            float2 ah1 = *(const float2*)&wa_h[8 * WS + ko];   // row q+8
            float2 al0 = *(const float2*)&wa_l[ko];
            float2 al1 = *(const float2*)&wa_l[8 * WS + ko];
            #pragma unroll
            for (int nf = 0; nf < 16; nf++) {
                float2 v = *(const float2*)&hb[nf * 8 * HS + ko];
                float bh0 = to_tf32(v.x), bh1 = to_tf32(v.y);
                float bl0 = to_tf32(v.x - bh0), bl1 = to_tf32(v.y - bh1);
                mma_tf32(acc[nf], ah0.x, ah1.x, ah0.y, ah1.y, bh0, bh1); // hi*hi
                mma_tf32(acc[nf], al0.x, al1.x, al0.y, al1.y, bh0, bh1); // lo*hi
                mma_tf32(acc[nf], ah0.x, ah1.x, ah0.y, ah1.y, bl0, bl1); // hi*lo
            }
        }
    }

    // Store acc -> hpT (tf32-rounded)
    {
        float* r0p = hpT + (dt * 16 + q) * HPT_S + mq * 128 + 2 * c;
        float* r1p = r0p + 8 * HPT_S;
        #pragma unroll
        for (int nf = 0; nf < 16; nf++) {
            *(float2*)&r0p[nf * 8] = make_float2(to_tf32(acc[nf][0]), to_tf32(acc[nf][1]));
            *(float2*)&r1p[nf * 8] = make_float2(to_tf32(acc[nf][2]), to_tf32(acc[nf][3]));
        }
    }
    __syncthreads();

    // =================== Phase 1.5: e-scores ===================
    {
        const int m = tid;
        float es = 0.f, ed = 0.f;
        #pragma unroll
        for (int d = 0; d < 64; d++) {
            float hp = hpT[d * HPT_S + m];
            es += hp * a_s[d];
            ed += hp * a_s[64 + d];
        }
        Ed_s[m]   = ex2(ed * LOG2E);
        Ed02_s[m] = ex2(ed * (NEG_SLOPE * LOG2E));
        Es_s[m]   = ex2(es * LOG2E);
        Es02_s[m] = ex2(es * (NEG_SLOPE * LOG2E));
    }
    __syncthreads();

    // =================== Phase 2: attention ===================
    // Warp owns rows [r0, r0+32) over the FULL 512-m scan.
    const int r0 = (warp >> 3) * 256 + (warp & 7) * 32 + q;
    const float EsA0 = Es_s[r0],        EsA1 = Es_s[r0 + 8];
    const float EtA0 = Es02_s[r0],      EtA1 = Es02_s[r0 + 8];
    const float EsB0 = Es_s[r0 + 16],   EsB1 = Es_s[r0 + 24];
    const float EtB0 = Es02_s[r0 + 16], EtB1 = Es02_s[r0 + 24];

    float dA[8][4], dB[8][4];
    #pragma unroll
    for (int t = 0; t < 8; t++)
        #pragma unroll
        for (int j = 0; j < 4; j++) { dA[t][j] = 0.f; dB[t][j] = 0.f; }

    float sA0 = 0.f, sA1 = 0.f, sB0 = 0.f, sB1 = 0.f;
    const float* bbase = hpT + q * HPT_S;

    #pragma unroll 2
    for (int k = 0; k < 64; k++) {
        const int m0 = k * 8 + 2 * c;   // k-permute: phys (c, c+4) -> m0, m0+1
        const float2 ed2 = *(const float2*)&Ed_s[m0];
        const float2 et2 = *(const float2*)&Ed02_s[m0];

        // A fragments: w = max(Es*Ed, Es02*Ed02) = exp(lrelu(es+ed))
        float a0 = fmaxf(EsA0 * ed2.x, EtA0 * et2.x);
        float a1 = fmaxf(EsA1 * ed2.x, EtA1 * et2.x);
        float a2 = fmaxf(EsA0 * ed2.y, EtA0 * et2.y);
        float a3 = fmaxf(EsA1 * ed2.y, EtA1 * et2.y);
        float a4 = fmaxf(EsB0 * ed2.x, EtB0 * et2.x);
        float a5 = fmaxf(EsB1 * ed2.x, EtB1 * et2.x);
        float a6 = fmaxf(EsB0 * ed2.y, EtB0 * et2.y);
        float a7 = fmaxf(EsB1 * ed2.y, EtB1 * et2.y);
        sA0 += a0 + a2; sA1 += a1 + a3;
        sB0 += a4 + a6; sB1 += a5 + a7;

        #pragma unroll
        for (int dtf = 0; dtf < 8; dtf++) {
            const float2 b2 = *(const float2*)&bbase[dtf * 8 * HPT_S + m0];
            mma_tf32(dA[dtf], a0, a1, a2, a3, b2.x, b2.y);
            mma_tf32(dB[dtf], a4, a5, a6, a7, b2.x, b2.y);
        }
    }

    // Row sums: reduce over the 4 k-lanes
    sA0 += __shfl_xor_sync(0xFFFFFFFFu, sA0, 1); sA0 += __shfl_xor_sync(0xFFFFFFFFu, sA0, 2);
    sA1 += __shfl_xor_sync(0xFFFFFFFFu, sA1, 1); sA1 += __shfl_xor_sync(0xFFFFFFFFu, sA1, 2);
    sB0 += __shfl_xor_sync(0xFFFFFFFFu, sB0, 1); sB0 += __shfl_xor_sync(0xFFFFFFFFu, sB0, 2);
    sB1 += __shfl_xor_sync(0xFFFFFFFFu, sB1, 1); sB1 += __shfl_xor_sync(0xFFFFFFFFu, sB1, 2);
    const float ivA0 = 1.f / sA0, ivA1 = 1.f / sA1;
    const float ivB0 = 1.f / sB0, ivB1 = 1.f / sB1;

    // Epilogue: normalize + ELU + store
    const size_t orow = ((size_t)bh * NA + r0) * HD;
    float* o0 = out + orow;                 // row r0
    float* o1 = o0 + 8 * HD;                // r0+8
    float* o2 = o0 + 16 * HD;               // r0+16
    float* o3 = o0 + 24 * HD;               // r0+24
    #pragma unroll
    for (int dtf = 0; dtf < 8; dtf++) {
        const int dc = dtf * 8 + 2 * c;
        float2 v;
        v.x = elu1(dA[dtf][0] * ivA0); v.y = elu1(dA[dtf][1] * ivA0);
        *(float2*)&o0[dc] = v;
        v.x = elu1(dA[dtf][2] * ivA1); v.y = elu1(dA[dtf][3] * ivA1);
        *(float2*)&o1[dc] = v;
        v.x = elu1(dB[dtf][0] * ivB0); v.y = elu1(dB[dtf][1] * ivB0);
        *(float2*)&o2[dc] = v;
        v.x = elu1(dB[dtf][2] * ivB1); v.y = elu1(dB[dtf][3] * ivB1);
        *(float2*)&o3[dc] = v;
    }
}

// ---------------------------------------------------------------------------
extern "C" void kernel_launch(void* const* d_in, const int* in_sizes, int n_in,
                              void* d_out, int out_size)
{
    const float* h     = (const float*)d_in[0];
    const float* W     = (const float*)d_in[1];
    const float* att_a = (const float*)d_in[2];
    float* out = (float*)d_out;

    cudaFuncSetAttribute(gat_fused_kernel,
        cudaFuncAttributeMaxDynamicSharedMemorySize, SMEM_F_BYTES);

    gat_fused_kernel<<<BS * NH, 512, SMEM_F_BYTES>>>(h, W, att_a, out);
}

// round 10
// speedup vs baseline: 1.2786x; 1.0480x over previous
#include <cuda_runtime.h>
#include <math.h>
#include <stdint.h>

#define NEG_SLOPE 0.2f
#define LOG2E 1.4426950408889634f

// Problem constants
#define BS 32
#define NA 512          // n_agents
#define ID 128          // input_dim
#define NH 8            // n_heads
#define HD 64           // hidden_dim

// ---------------------------------------------------------------------------
// helpers
// ---------------------------------------------------------------------------
__device__ __forceinline__ float to_tf32(float x) {
    uint32_t u;
    asm("cvt.rn.tf32.f32 %0, %1;" : "=r"(u) : "f"(x));
    return __uint_as_float(u);
}
__device__ __forceinline__ float ex2(float x) {
    float r;
    asm("ex2.approx.f32 %0, %1;" : "=f"(r) : "f"(x));
    return r;
}
__device__ __forceinline__ uint32_t smem_u32(const void* p) {
    uint32_t a;
    asm("{ .reg .u64 t; cvta.to.shared.u64 t, %1; cvt.u32.u64 %0, t; }"
        : "=r"(a) : "l"(p));
    return a;
}
__device__ __forceinline__ void cp_async16(uint32_t dst, const void* src) {
    asm volatile("cp.async.cg.shared.global [%0], [%1], 16;"
                 :: "r"(dst), "l"(src) : "memory");
}
#define CP_COMMIT() asm volatile("cp.async.commit_group;" ::: "memory")
#define CP_WAIT(n)  asm volatile("cp.async.wait_group %0;" :: "n"(n) : "memory")

__device__ __forceinline__ void mma_tf32(float d[4], float a0, float a1,
                                         float a2, float a3, float b0, float b1) {
    asm volatile(
        "mma.sync.aligned.m16n8k8.row.col.f32.tf32.tf32.f32 "
        "{%0,%1,%2,%3}, {%4,%5,%6,%7}, {%8,%9}, {%0,%1,%2,%3};"
        : "+f"(d[0]), "+f"(d[1]), "+f"(d[2]), "+f"(d[3])
        : "r"(__float_as_uint(a0)), "r"(__float_as_uint(a1)),
          "r"(__float_as_uint(a2)), "r"(__float_as_uint(a3)),
          "r"(__float_as_uint(b0)), "r"(__float_as_uint(b1)));
}
__device__ __forceinline__ float elu1(float x) {
    return x > 0.f ? x : expm1f(x);
}

// ---------------------------------------------------------------------------
// Fused kernel: one CTA per (b, head). 512 threads = 16 warps.
// Phase 1: hpT = W^T @ h^T (split-tf32, 3 products), h staged via cp.async
//          double buffer, W fragments via per-warp LDG + register hi/lo.
// Phase 1.5: e-scores -> exp factors.
// Phase 2: R9 attention loop (warp = 32 rows x full 512-m scan).
// ---------------------------------------------------------------------------
#define HPT_S 516
#define HS 20               // h stage stride (rows 16B-aligned: 80B)
#define KC 16               // k-chunk

#define SM_HPT   0
#define SM_HSTG  (64 * HPT_S)              // h_s [2][512][HS]
#define SM_ED    (SM_HSTG + 2 * 512 * HS)  // [512]
#define SM_ED02  (SM_ED + 512)
#define SM_ES    (SM_ED02 + 512)
#define SM_ES02  (SM_ES + 512)
#define SM_A     (SM_ES02 + 512)           // [128]
#define SMEM_F_FLOATS (SM_A + 128 + 8)
#define SMEM_F_BYTES (SMEM_F_FLOATS * 4)   // 222,752 B

__global__ void __launch_bounds__(512, 1) gat_fused_kernel(
    const float* __restrict__ h, const float* __restrict__ W,
    const float* __restrict__ att_a, float* __restrict__ out)
{
    extern __shared__ float sm[];
    float* hpT    = sm + SM_HPT;
    float* h_s    = sm + SM_HSTG;
    float* Ed_s   = sm + SM_ED;
    float* Ed02_s = sm + SM_ED02;
    float* Es_s   = sm + SM_ES;
    float* Es02_s = sm + SM_ES02;
    float* a_s    = sm + SM_A;

    const int bh = blockIdx.x;
    const int head = bh & 7;
    const int b = bh >> 3;
    const int col0 = head * HD;
    const int tid = threadIdx.x;
    const int warp = tid >> 5;
    const int lane = tid & 31;
    const int q = lane >> 2;       // group id
    const int c = lane & 3;        // k position / col pair

    if (tid < 128) a_s[tid] = att_a[head * 128 + tid];

    // ======================= Phase 1: GEMM -> hpT =======================
    const int dt = warp & 3;       // d-tile: rows dt*16 + {q, q+8}
    const int mq = warp >> 2;      // m-quarter: cols mq*128 + nf*8

    float acc[16][4];
    #pragma unroll
    for (int f = 0; f < 16; f++)
        #pragma unroll
        for (int j = 0; j < 4; j++) acc[f][j] = 0.f;

    const float* hrow = h + ((size_t)(b * NA) + tid) * ID;
    const uint32_t hdst = smem_u32(h_s) + tid * (HS * 4);
    const int hb_off = (mq * 128 + q) * HS + 2 * c;

    // prologue: stage chunk 0 into buf 0
    #pragma unroll
    for (int i = 0; i < 4; i++)
        cp_async16(hdst + i * 16, hrow + i * 4);
    CP_COMMIT();

    // W fragment base for this warp's rows (d0 = dt*16+q, d0+8)
    const float* wp = W + col0 + dt * 16 + q;

    for (int kc = 0; kc < 8; kc++) {
        if (kc + 1 < 8) {
            const float* src = hrow + (kc + 1) * KC;
            const uint32_t dst = hdst + ((kc + 1) & 1) * (512 * HS * 4);
            #pragma unroll
            for (int i = 0; i < 4; i++)
                cp_async16(dst + i * 16, src + i * 4);
            CP_COMMIT();
            CP_WAIT(1);
        } else {
            CP_WAIT(0);
        }
        __syncthreads();   // chunk kc visible to all

        // W fragments for this chunk: 8 LDG.32 (L1-hot) + register hi/lo
        const float* wk = wp + (size_t)(kc * KC) * 512;
        float ah[2][2][2], al[2][2][2];   // [ks][row01][kpair01]
        #pragma unroll
        for (int ks = 0; ks < 2; ks++) {
            #pragma unroll
            for (int j = 0; j < 2; j++) {
                float w0 = wk[(size_t)(ks * 8 + 2 * c + j) * 512];       // row q
                float w1 = wk[(size_t)(ks * 8 + 2 * c + j) * 512 + 8];   // row q+8
                float h0 = to_tf32(w0), h1 = to_tf32(w1);
                ah[ks][0][j] = h0; al[ks][0][j] = to_tf32(w0 - h0);
                ah[ks][1][j] = h1; al[ks][1][j] = to_tf32(w1 - h1);
            }
        }

        const float* hb = h_s + (kc & 1) * (512 * HS) + hb_off;
        #pragma unroll
        for (int ks = 0; ks < 2; ks++) {
            const int ko = ks * 8;
            #pragma unroll
            for (int nf = 0; nf < 16; nf++) {
                float2 v = *(const float2*)&hb[nf * 8 * HS + ko];
                float bh0 = to_tf32(v.x), bh1 = to_tf32(v.y);
                float bl0 = to_tf32(v.x - bh0), bl1 = to_tf32(v.y - bh1);
                mma_tf32(acc[nf], ah[ks][0][0], ah[ks][1][0], ah[ks][0][1], ah[ks][1][1], bh0, bh1); // hi*hi
                mma_tf32(acc[nf], al[ks][0][0], al[ks][1][0], al[ks][0][1], al[ks][1][1], bh0, bh1); // lo*hi
                mma_tf32(acc[nf], ah[ks][0][0], ah[ks][1][0], ah[ks][0][1], ah[ks][1][1], bl0, bl1); // hi*lo
            }
        }
        __syncthreads();   // all warps done with buf kc&1 before it is overwritten
    }

    // Store acc -> hpT (tf32-rounded)
    {
        float* r0p = hpT + (dt * 16 + q) * HPT_S + mq * 128 + 2 * c;
        float* r1p = r0p + 8 * HPT_S;
        #pragma unroll
        for (int nf = 0; nf < 16; nf++) {
            *(float2*)&r0p[nf * 8] = make_float2(to_tf32(acc[nf][0]), to_tf32(acc[nf][1]));
            *(float2*)&r1p[nf * 8] = make_float2(to_tf32(acc[nf][2]), to_tf32(acc[nf][3]));
        }
    }
    __syncthreads();

    // =================== Phase 1.5: e-scores ===================
    {
        const int m = tid;
        float es = 0.f, ed = 0.f;
        #pragma unroll
        for (int d = 0; d < 64; d++) {
            float hp = hpT[d * HPT_S + m];
            es += hp * a_s[d];
            ed += hp * a_s[64 + d];
        }
        Ed_s[m]   = ex2(ed * LOG2E);
        Ed02_s[m] = ex2(ed * (NEG_SLOPE * LOG2E));
        Es_s[m]   = ex2(es * LOG2E);
        Es02_s[m] = ex2(es * (NEG_SLOPE * LOG2E));
    }
    __syncthreads();

    // =================== Phase 2: attention ===================
    const int r0 = (warp >> 3) * 256 + (warp & 7) * 32 + q;
    const float EsA0 = Es_s[r0],        EsA1 = Es_s[r0 + 8];
    const float EtA0 = Es02_s[r0],      EtA1 = Es02_s[r0 + 8];
    const float EsB0 = Es_s[r0 + 16],   EsB1 = Es_s[r0 + 24];
    const float EtB0 = Es02_s[r0 + 16], EtB1 = Es02_s[r0 + 24];

    float dA[8][4], dB[8][4];
    #pragma unroll
    for (int t = 0; t < 8; t++)
        #pragma unroll
        for (int j = 0; j < 4; j++) { dA[t][j] = 0.f; dB[t][j] = 0.f; }

    float sA0 = 0.f, sA1 = 0.f, sB0 = 0.f, sB1 = 0.f;
    const float* bbase = hpT + q * HPT_S;

    #pragma unroll 2
    for (int k = 0; k < 64; k++) {
        const int m0 = k * 8 + 2 * c;   // k-permute: phys (c, c+4) -> m0, m0+1
        const float2 ed2 = *(const float2*)&Ed_s[m0];
        const float2 et2 = *(const float2*)&Ed02_s[m0];

        float a0 = fmaxf(EsA0 * ed2.x, EtA0 * et2.x);
        float a1 = fmaxf(EsA1 * ed2.x, EtA1 * et2.x);
        float a2 = fmaxf(EsA0 * ed2.y, EtA0 * et2.y);
        float a3 = fmaxf(EsA1 * ed2.y, EtA1 * et2.y);
        float a4 = fmaxf(EsB0 * ed2.x, EtB0 * et2.x);
        float a5 = fmaxf(EsB1 * ed2.x, EtB1 * et2.x);
        float a6 = fmaxf(EsB0 * ed2.y, EtB0 * et2.y);
        float a7 = fmaxf(EsB1 * ed2.y, EtB1 * et2.y);
        sA0 += a0 + a2; sA1 += a1 + a3;
        sB0 += a4 + a6; sB1 += a5 + a7;

        #pragma unroll
        for (int dtf = 0; dtf < 8; dtf++) {
            const float2 b2 = *(const float2*)&bbase[dtf * 8 * HPT_S + m0];
            mma_tf32(dA[dtf], a0, a1, a2, a3, b2.x, b2.y);
            mma_tf32(dB[dtf], a4, a5, a6, a7, b2.x, b2.y);
        }
    }

    // Row sums: reduce over the 4 k-lanes
    sA0 += __shfl_xor_sync(0xFFFFFFFFu, sA0, 1); sA0 += __shfl_xor_sync(0xFFFFFFFFu, sA0, 2);
    sA1 += __shfl_xor_sync(0xFFFFFFFFu, sA1, 1); sA1 += __shfl_xor_sync(0xFFFFFFFFu, sA1, 2);
    sB0 += __shfl_xor_sync(0xFFFFFFFFu, sB0, 1); sB0 += __shfl_xor_sync(0xFFFFFFFFu, sB0, 2);
    sB1 += __shfl_xor_sync(0xFFFFFFFFu, sB1, 1); sB1 += __shfl_xor_sync(0xFFFFFFFFu, sB1, 2);
    const float ivA0 = 1.f / sA0, ivA1 = 1.f / sA1;
    const float ivB0 = 1.f / sB0, ivB1 = 1.f / sB1;

    // Epilogue: normalize + ELU + store
    const size_t orow = ((size_t)bh * NA + r0) * HD;
    float* o0 = out + orow;                 // row r0
    float* o1 = o0 + 8 * HD;                // r0+8
    float* o2 = o0 + 16 * HD;               // r0+16
    float* o3 = o0 + 24 * HD;               // r0+24
    #pragma unroll
    for (int dtf = 0; dtf < 8; dtf++) {
        const int dc = dtf * 8 + 2 * c;
        float2 v;
        v.x = elu1(dA[dtf][0] * ivA0); v.y = elu1(dA[dtf][1] * ivA0);
        *(float2*)&o0[dc] = v;
        v.x = elu1(dA[dtf][2] * ivA1); v.y = elu1(dA[dtf][3] * ivA1);
        *(float2*)&o1[dc] = v;
        v.x = elu1(dB[dtf][0] * ivB0); v.y = elu1(dB[dtf][1] * ivB0);
        *(float2*)&o2[dc] = v;
        v.x = elu1(dB[dtf][2] * ivB1); v.y = elu1(dB[dtf][3] * ivB1);
        *(float2*)&o3[dc] = v;
    }
}

// ---------------------------------------------------------------------------
extern "C" void kernel_launch(void* const* d_in, const int* in_sizes, int n_in,
                              void* d_out, int out_size)
{
    const float* h     = (const float*)d_in[0];
    const float* W     = (const float*)d_in[1];
    const float* att_a = (const float*)d_in[2];
    float* out = (float*)d_out;

    cudaFuncSetAttribute(gat_fused_kernel,
        cudaFuncAttributeMaxDynamicSharedMemorySize, SMEM_F_BYTES);

    gat_fused_kernel<<<BS * NH, 512, SMEM_F_BYTES>>>(h, W, att_a, out);
}

// round 11
// speedup vs baseline: 1.2971x; 1.0145x over previous
#include <cuda_runtime.h>
#include <math.h>
#include <stdint.h>

#define NEG_SLOPE 0.2f
#define LOG2E 1.4426950408889634f

// Problem constants
#define BS 32
#define NA 512          // n_agents
#define ID 128          // input_dim
#define NH 8            // n_heads
#define HD 64           // hidden_dim

// ---------------------------------------------------------------------------
// helpers
// ---------------------------------------------------------------------------
__device__ __forceinline__ float to_tf32(float x) {
    uint32_t u;
    asm("cvt.rn.tf32.f32 %0, %1;" : "=r"(u) : "f"(x));
    return __uint_as_float(u);
}
__device__ __forceinline__ float ex2(float x) {
    float r;
    asm("ex2.approx.f32 %0, %1;" : "=f"(r) : "f"(x));
    return r;
}
__device__ __forceinline__ uint32_t smem_u32(const void* p) {
    uint32_t a;
    asm("{ .reg .u64 t; cvta.to.shared.u64 t, %1; cvt.u32.u64 %0, t; }"
        : "=r"(a) : "l"(p));
    return a;
}
__device__ __forceinline__ void cp_async16(uint32_t dst, const void* src) {
    asm volatile("cp.async.cg.shared.global [%0], [%1], 16;"
                 :: "r"(dst), "l"(src) : "memory");
}
#define CP_COMMIT() asm volatile("cp.async.commit_group;" ::: "memory")
#define CP_WAIT(n)  asm volatile("cp.async.wait_group %0;" :: "n"(n) : "memory")

__device__ __forceinline__ void mma_tf32(float d[4], float a0, float a1,
                                         float a2, float a3, float b0, float b1) {
    asm volatile(
        "mma.sync.aligned.m16n8k8.row.col.f32.tf32.tf32.f32 "
        "{%0,%1,%2,%3}, {%4,%5,%6,%7}, {%8,%9}, {%0,%1,%2,%3};"
        : "+f"(d[0]), "+f"(d[1]), "+f"(d[2]), "+f"(d[3])
        : "r"(__float_as_uint(a0)), "r"(__float_as_uint(a1)),
          "r"(__float_as_uint(a2)), "r"(__float_as_uint(a3)),
          "r"(__float_as_uint(b0)), "r"(__float_as_uint(b1)));
}
__device__ __forceinline__ float elu1(float x) {
    return x > 0.f ? x : expm1f(x);
}

// ---------------------------------------------------------------------------
// Fused kernel: one CTA per (b, head). 512 threads = 16 warps.
// hpT is stored with an m-permuted layout: within each 16-m block,
//   phys = c*4 + s*2 + j  <->  logical = s*8 + c*2 + j   (c=pair,s=slab,j=elem)
// so phase-2 B-fragments for two consecutive k8 slabs form one float4.
// ---------------------------------------------------------------------------
#define HPT_S 516
#define HS 20               // h stage stride (rows 16B-aligned: 80B)
#define KC 16               // k-chunk

#define SM_HPT   0
#define SM_HSTG  (64 * HPT_S)              // h_s [2][512][HS]
#define SM_EDP   (SM_HSTG + 2 * 512 * HS)  // Edp [256] float4
#define SM_ES    (SM_EDP + 1024)           // [512]
#define SM_ES02  (SM_ES + 512)             // [512]
#define SM_A     (SM_ES02 + 512)           // [128]
#define SMEM_F_FLOATS (SM_A + 128 + 8)
#define SMEM_F_BYTES (SMEM_F_FLOATS * 4)   // 222,752 B

__global__ void __launch_bounds__(512, 1) gat_fused_kernel(
    const float* __restrict__ h, const float* __restrict__ W,
    const float* __restrict__ att_a, float* __restrict__ out)
{
    extern __shared__ float sm[];
    float*  hpT    = sm + SM_HPT;
    float*  h_s    = sm + SM_HSTG;
    float4* Edp    = (float4*)(sm + SM_EDP);
    float*  Es_s   = sm + SM_ES;
    float*  Es02_s = sm + SM_ES02;
    float*  a_s    = sm + SM_A;

    const int bh = blockIdx.x;
    const int head = bh & 7;
    const int b = bh >> 3;
    const int col0 = head * HD;
    const int tid = threadIdx.x;
    const int warp = tid >> 5;
    const int lane = tid & 31;
    const int q = lane >> 2;       // group id
    const int c = lane & 3;        // k position / col pair

    if (tid < 128) a_s[tid] = att_a[head * 128 + tid];

    // ======================= Phase 1: GEMM -> hpT =======================
    const int dt = warp & 3;       // d-tile: rows dt*16 + {q, q+8}
    const int mq = warp >> 2;      // m-quarter: cols mq*128 + nf*8

    float acc[16][4];
    #pragma unroll
    for (int f = 0; f < 16; f++)
        #pragma unroll
        for (int j = 0; j < 4; j++) acc[f][j] = 0.f;

    const float* hrow = h + ((size_t)(b * NA) + tid) * ID;
    const uint32_t hdst = smem_u32(h_s) + tid * (HS * 4);
    const int hb_off = (mq * 128 + q) * HS + 2 * c;
    const float* wp = W + col0 + dt * 16 + q;

    // prologue: stage chunk 0 into buf 0
    #pragma unroll
    for (int i = 0; i < 4; i++)
        cp_async16(hdst + i * 16, hrow + i * 4);
    CP_COMMIT();

    for (int kc = 0; kc < 8; kc++) {
        CP_WAIT(0);          // my chunk-kc rows are in SMEM
        __syncthreads();     // everyone's rows visible; prev buf fully consumed

        if (kc + 1 < 8) {
            const float* src = hrow + (kc + 1) * KC;
            const uint32_t dst = hdst + ((kc + 1) & 1) * (512 * HS * 4);
            #pragma unroll
            for (int i = 0; i < 4; i++)
                cp_async16(dst + i * 16, src + i * 4);
            CP_COMMIT();
        }

        // W fragments: 8 LDG.32 (L1-hot) + register hi/lo split
        const float* wk = wp + (size_t)(kc * KC) * 512;
        float ah[2][2][2], al[2][2][2];   // [ks][row01][kpair01]
        #pragma unroll
        for (int ks = 0; ks < 2; ks++) {
            #pragma unroll
            for (int j = 0; j < 2; j++) {
                float w0 = wk[(size_t)(ks * 8 + 2 * c + j) * 512];       // row q
                float w1 = wk[(size_t)(ks * 8 + 2 * c + j) * 512 + 8];   // row q+8
                float h0 = to_tf32(w0), h1 = to_tf32(w1);
                ah[ks][0][j] = h0; al[ks][0][j] = to_tf32(w0 - h0);
                ah[ks][1][j] = h1; al[ks][1][j] = to_tf32(w1 - h1);
            }
        }

        const float* hb = h_s + (kc & 1) * (512 * HS) + hb_off;
        #pragma unroll
        for (int ks = 0; ks < 2; ks++) {
            const int ko = ks * 8;
            #pragma unroll
            for (int nf = 0; nf < 16; nf++) {
                float2 v = *(const float2*)&hb[nf * 8 * HS + ko];
                float bh0 = to_tf32(v.x), bh1 = to_tf32(v.y);
                float bl0 = to_tf32(v.x - bh0), bl1 = to_tf32(v.y - bh1);
                mma_tf32(acc[nf], ah[ks][0][0], ah[ks][1][0], ah[ks][0][1], ah[ks][1][1], bh0, bh1); // hi*hi
                mma_tf32(acc[nf], al[ks][0][0], al[ks][1][0], al[ks][0][1], al[ks][1][1], bh0, bh1); // lo*hi
                mma_tf32(acc[nf], ah[ks][0][0], ah[ks][1][0], ah[ks][0][1], ah[ks][1][1], bl0, bl1); // hi*lo
            }
        }
    }
    __syncthreads();   // last buf consumed; (also orders before hpT stores)

    // Store acc -> hpT (tf32-rounded) in the PERMUTED layout:
    //   logical m = mq*128 + nf*8 + 2c + j
    //   phys      = mq*128 + (nf>>1)*16 + c*4 + (nf&1)*2 + j
    {
        float* r0p = hpT + (dt * 16 + q) * HPT_S + mq * 128 + c * 4;
        float* r1p = r0p + 8 * HPT_S;
        #pragma unroll
        for (int nf = 0; nf < 16; nf++) {
            const int off = (nf >> 1) * 16 + (nf & 1) * 2;
            *(float2*)&r0p[off] = make_float2(to_tf32(acc[nf][0]), to_tf32(acc[nf][1]));
            *(float2*)&r1p[off] = make_float2(to_tf32(acc[nf][2]), to_tf32(acc[nf][3]));
        }
    }
    __syncthreads();

    // =================== Phase 1.5: e-scores ===================
    // Thread handles PHYSICAL column tid; its logical agent:
    {
        const int w = tid & 15;
        const int a = (tid & ~15) | (((w >> 1) & 1) << 3) | ((w >> 2) << 1) | (w & 1);
        float es = 0.f, ed = 0.f;
        #pragma unroll
        for (int d = 0; d < 64; d++) {
            float hp = hpT[d * HPT_S + tid];
            es += hp * a_s[d];
            ed += hp * a_s[64 + d];
        }
        Es_s[a]   = ex2(es * LOG2E);
        Es02_s[a] = ex2(es * (NEG_SLOPE * LOG2E));
        float* ep = (float*)&Edp[tid >> 1];
        const int j = tid & 1;
        ep[j]     = ex2(ed * LOG2E);
        ep[2 + j] = ex2(ed * (NEG_SLOPE * LOG2E));
    }
    __syncthreads();

    // =================== Phase 2: attention ===================
    const int r0 = (warp >> 3) * 256 + (warp & 7) * 32 + q;
    const float EsA0 = Es_s[r0],        EsA1 = Es_s[r0 + 8];
    const float EtA0 = Es02_s[r0],      EtA1 = Es02_s[r0 + 8];
    const float EsB0 = Es_s[r0 + 16],   EsB1 = Es_s[r0 + 24];
    const float EtB0 = Es02_s[r0 + 16], EtB1 = Es02_s[r0 + 24];

    float dA[8][4], dB[8][4];
    #pragma unroll
    for (int t = 0; t < 8; t++)
        #pragma unroll
        for (int j = 0; j < 4; j++) { dA[t][j] = 0.f; dB[t][j] = 0.f; }

    float sA0 = 0.f, sA1 = 0.f, sB0 = 0.f, sB1 = 0.f;
    const float*  bbase = hpT + q * HPT_S + c * 4;
    const float4* edp   = Edp + 2 * c;

    #pragma unroll 2
    for (int K = 0; K < 32; K++) {          // k-pair = two k8 slabs
        const float4 e0 = edp[K * 8];       // slab0: Ed(m0),Ed(m1),Ed02(m0),Ed02(m1)
        const float4 e1 = edp[K * 8 + 1];   // slab1

        // A fragments slab0: w = max(Es*Ed, Es02*Ed02)
        float a0 = fmaxf(EsA0 * e0.x, EtA0 * e0.z);
        float a1 = fmaxf(EsA1 * e0.x, EtA1 * e0.z);
        float a2 = fmaxf(EsA0 * e0.y, EtA0 * e0.w);
        float a3 = fmaxf(EsA1 * e0.y, EtA1 * e0.w);
        float a4 = fmaxf(EsB0 * e0.x, EtB0 * e0.z);
        float a5 = fmaxf(EsB1 * e0.x, EtB1 * e0.z);
        float a6 = fmaxf(EsB0 * e0.y, EtB0 * e0.w);
        float a7 = fmaxf(EsB1 * e0.y, EtB1 * e0.w);
        // A fragments slab1
        float g0 = fmaxf(EsA0 * e1.x, EtA0 * e1.z);
        float g1 = fmaxf(EsA1 * e1.x, EtA1 * e1.z);
        float g2 = fmaxf(EsA0 * e1.y, EtA0 * e1.w);
        float g3 = fmaxf(EsA1 * e1.y, EtA1 * e1.w);
        float g4 = fmaxf(EsB0 * e1.x, EtB0 * e1.z);
        float g5 = fmaxf(EsB1 * e1.x, EtB1 * e1.z);
        float g6 = fmaxf(EsB0 * e1.y, EtB0 * e1.w);
        float g7 = fmaxf(EsB1 * e1.y, EtB1 * e1.w);

        sA0 += (a0 + a2) + (g0 + g2);
        sA1 += (a1 + a3) + (g1 + g3);
        sB0 += (a4 + a6) + (g4 + g6);
        sB1 += (a5 + a7) + (g5 + g7);

        const float* bk = bbase + K * 16;
        #pragma unroll
        for (int dtf = 0; dtf < 8; dtf++) {
            const float4 b4 = *(const float4*)&bk[dtf * 8 * HPT_S];
            mma_tf32(dA[dtf], a0, a1, a2, a3, b4.x, b4.y);   // slab0
            mma_tf32(dB[dtf], a4, a5, a6, a7, b4.x, b4.y);
            mma_tf32(dA[dtf], g0, g1, g2, g3, b4.z, b4.w);   // slab1
            mma_tf32(dB[dtf], g4, g5, g6, g7, b4.z, b4.w);
        }
    }

    // Row sums: reduce over the 4 k-lanes
    sA0 += __shfl_xor_sync(0xFFFFFFFFu, sA0, 1); sA0 += __shfl_xor_sync(0xFFFFFFFFu, sA0, 2);
    sA1 += __shfl_xor_sync(0xFFFFFFFFu, sA1, 1); sA1 += __shfl_xor_sync(0xFFFFFFFFu, sA1, 2);
    sB0 += __shfl_xor_sync(0xFFFFFFFFu, sB0, 1); sB0 += __shfl_xor_sync(0xFFFFFFFFu, sB0, 2);
    sB1 += __shfl_xor_sync(0xFFFFFFFFu, sB1, 1); sB1 += __shfl_xor_sync(0xFFFFFFFFu, sB1, 2);
    const float ivA0 = 1.f / sA0, ivA1 = 1.f / sA1;
    const float ivB0 = 1.f / sB0, ivB1 = 1.f / sB1;

    // Epilogue: normalize + ELU + store
    const size_t orow = ((size_t)bh * NA + r0) * HD;
    float* o0 = out + orow;                 // row r0
    float* o1 = o0 + 8 * HD;                // r0+8
    float* o2 = o0 + 16 * HD;               // r0+16
    float* o3 = o0 + 24 * HD;               // r0+24
    #pragma unroll
    for (int dtf = 0; dtf < 8; dtf++) {
        const int dc = dtf * 8 + 2 * c;
        float2 v;
        v.x = elu1(dA[dtf][0] * ivA0); v.y = elu1(dA[dtf][1] * ivA0);
        *(float2*)&o0[dc] = v;
        v.x = elu1(dA[dtf][2] * ivA1); v.y = elu1(dA[dtf][3] * ivA1);
        *(float2*)&o1[dc] = v;
        v.x = elu1(dB[dtf][0] * ivB0); v.y = elu1(dB[dtf][1] * ivB0);
        *(float2*)&o2[dc] = v;
        v.x = elu1(dB[dtf][2] * ivB1); v.y = elu1(dB[dtf][3] * ivB1);
        *(float2*)&o3[dc] = v;
    }
}

// ---------------------------------------------------------------------------
extern "C" void kernel_launch(void* const* d_in, const int* in_sizes, int n_in,
                              void* d_out, int out_size)
{
    const float* h     = (const float*)d_in[0];
    const float* W     = (const float*)d_in[1];
    const float* att_a = (const float*)d_in[2];
    float* out = (float*)d_out;

    cudaFuncSetAttribute(gat_fused_kernel,
        cudaFuncAttributeMaxDynamicSharedMemorySize, SMEM_F_BYTES);

    gat_fused_kernel<<<BS * NH, 512, SMEM_F_BYTES>>>(h, W, att_a, out);
}

// round 12
// speedup vs baseline: 1.7485x; 1.3480x over previous
#include <cuda_runtime.h>
#include <cuda_fp16.h>
#include <cuda_bf16.h>
#include <math.h>
#include <stdint.h>

#define NEG_SLOPE 0.2f
#define LOG2E 1.4426950408889634f

// Problem constants
#define BS 32
#define NA 512          // n_agents
#define ID 128          // input_dim
#define NH 8            // n_heads
#define HD 64           // hidden_dim

// ---------------------------------------------------------------------------
// helpers
// ---------------------------------------------------------------------------
__device__ __forceinline__ float ex2(float x) {
    float r;
    asm("ex2.approx.f32 %0, %1;" : "=f"(r) : "f"(x));
    return r;
}
__device__ __forceinline__ uint32_t smem_u32(const void* p) {
    uint32_t a;
    asm("{ .reg .u64 t; cvta.to.shared.u64 t, %1; cvt.u32.u64 %0, t; }"
        : "=r"(a) : "l"(p));
    return a;
}
__device__ __forceinline__ void cp_async16(uint32_t dst, const void* src) {
    asm volatile("cp.async.cg.shared.global [%0], [%1], 16;"
                 :: "r"(dst), "l"(src) : "memory");
}
#define CP_COMMIT() asm volatile("cp.async.commit_group;" ::: "memory")
#define CP_WAIT0()  asm volatile("cp.async.wait_group 0;" ::: "memory")

__device__ __forceinline__ void mma_f16(float d[4], uint32_t a0, uint32_t a1,
                                        uint32_t a2, uint32_t a3,
                                        uint32_t b0, uint32_t b1) {
    asm volatile(
        "mma.sync.aligned.m16n8k16.row.col.f32.f16.f16.f32 "
        "{%0,%1,%2,%3}, {%4,%5,%6,%7}, {%8,%9}, {%0,%1,%2,%3};"
        : "+f"(d[0]), "+f"(d[1]), "+f"(d[2]), "+f"(d[3])
        : "r"(a0), "r"(a1), "r"(a2), "r"(a3), "r"(b0), "r"(b1));
}
__device__ __forceinline__ void mma_bf16(float d[4], uint32_t a0, uint32_t a1,
                                         uint32_t a2, uint32_t a3,
                                         uint32_t b0, uint32_t b1) {
    asm volatile(
        "mma.sync.aligned.m16n8k16.row.col.f32.bf16.bf16.f32 "
        "{%0,%1,%2,%3}, {%4,%5,%6,%7}, {%8,%9}, {%0,%1,%2,%3};"
        : "+f"(d[0]), "+f"(d[1]), "+f"(d[2]), "+f"(d[3])
        : "r"(a0), "r"(a1), "r"(a2), "r"(a3), "r"(b0), "r"(b1));
}
__device__ __forceinline__ float elu1(float x) {
    return x > 0.f ? x : expm1f(x);
}
__device__ __forceinline__ uint32_t h2u(__half2 v) {
    return *reinterpret_cast<uint32_t*>(&v);
}
__device__ __forceinline__ uint32_t b2u(__nv_bfloat162 v) {
    return *reinterpret_cast<uint32_t*>(&v);
}

// ---------------------------------------------------------------------------
// SMEM layout (byte offsets). k/m positions within each 16-group are stored
// PERMUTED to match m16n8k16 fragments: phys c*4+{0,1,2,3} = logical
// {2c, 2c+1, 2c+8, 2c+9}.
// ---------------------------------------------------------------------------
#define HPTH_S 528          // hpT fp16 row stride (1056B = 32 mod 128: 2-way ok)
#define HS32 20             // fp32 h staging stride
#define WS16 136            // W bf16 row stride (272B)

#define OFF_HPT   0                                   // __half  [64][528]
#define OFF_WH    (OFF_HPT + 64 * HPTH_S * 2)         // bf16 [64][136]  67584
#define OFF_WL    (OFF_WH + 64 * WS16 * 2)            //                 84992
#define OFF_H16H  (OFF_WL + 64 * WS16 * 2)            // bf16 [512][16] 102400
#define OFF_H16L  (OFF_H16H + 512 * 16 * 2)           //                118784
#define OFF_HS32  (OFF_H16L + 512 * 16 * 2)           // float [512][20] 135168
#define OFF_EDP   (OFF_HS32 + 512 * HS32 * 4)         // float4 [256]   176128
#define OFF_ES    (OFF_EDP + 256 * 16)                // float [512]
#define OFF_ES02  (OFF_ES + 512 * 4)
#define OFF_AS    (OFF_ES02 + 512 * 4)                // float [128]
#define OFF_RED   (OFF_AS + 128 * 4)                  // float [16]
#define SMEM_F_BYTES (OFF_RED + 64 + 64)

__global__ void __launch_bounds__(512, 1) gat_fused_kernel(
    const float* __restrict__ h, const float* __restrict__ W,
    const float* __restrict__ att_a, float* __restrict__ out)
{
    extern __shared__ char smraw[];
    __half*         hpT  = (__half*)(smraw + OFF_HPT);
    __nv_bfloat16*  Wh16 = (__nv_bfloat16*)(smraw + OFF_WH);
    __nv_bfloat16*  Wl16 = (__nv_bfloat16*)(smraw + OFF_WL);
    char*           h16h = smraw + OFF_H16H;   // bf16, byte-addressed
    char*           h16l = smraw + OFF_H16L;
    float*          h_s32 = (float*)(smraw + OFF_HS32);
    float4*         Edp  = (float4*)(smraw + OFF_EDP);
    float*          Es_s = (float*)(smraw + OFF_ES);
    float*          Es02_s = (float*)(smraw + OFF_ES02);
    float*          a_s  = (float*)(smraw + OFF_AS);
    float*          red_s = (float*)(smraw + OFF_RED);

    const int bh = blockIdx.x;
    const int head = bh & 7;
    const int b = bh >> 3;
    const int col0 = head * HD;
    const int tid = threadIdx.x;
    const int warp = tid >> 5;
    const int lane = tid & 31;
    const int q = lane >> 2;       // group id
    const int c = lane & 3;        // thread-in-group

    if (tid < 128) a_s[tid] = att_a[head * 128 + tid];

    // ---- Stage & split W into bf16 hi/lo (permuted k), once ----
    #pragma unroll 4
    for (int i = 0; i < 16; i++) {
        int idx = tid + i * 512;
        int d = idx & 63, k = idx >> 6;
        float v = W[(size_t)k * 512 + col0 + d];
        __nv_bfloat16 hi = __float2bfloat16_rn(v);
        __nv_bfloat16 lo = __float2bfloat16_rn(v - __bfloat162float(hi));
        int L = k & 15;
        int pk = (k & ~15) + ((L >> 1) & 3) * 4 + (L >> 3) * 2 + (L & 1);
        Wh16[d * WS16 + pk] = hi;
        Wl16[d * WS16 + pk] = lo;
    }

    // ---- prologue: cp.async chunk 0 of h (fp32) ----
    const float* hrow = h + ((size_t)(b * NA) + tid) * ID;
    const uint32_t hdst = smem_u32(h_s32) + tid * (HS32 * 4);
    #pragma unroll
    for (int i = 0; i < 4; i++)
        cp_async16(hdst + i * 16, hrow + i * 4);
    CP_COMMIT();

    // ======================= Phase 1: GEMM -> hpT =======================
    const int dt = warp & 3;       // d-tile: rows dt*16 + {q, q+8}
    const int mq = warp >> 2;      // m-quarter
    const int row0 = dt * 16 + q;

    float acc[16][4];
    #pragma unroll
    for (int f = 0; f < 16; f++)
        #pragma unroll
        for (int j = 0; j < 4; j++) acc[f][j] = 0.f;

    for (int kc = 0; kc < 8; kc++) {
        CP_WAIT0();
        __syncthreads();   // h_s32 chunk kc ready; prior MMA/split complete

        // split own row's 16 values -> bf16 hi/lo (permuted)
        {
            float v[16];
            #pragma unroll
            for (int i = 0; i < 4; i++)
                *(float4*)&v[i * 4] = *(const float4*)&h_s32[tid * HS32 + i * 4];
            #pragma unroll
            for (int cc = 0; cc < 4; cc++) {
                float v0 = v[2 * cc], v1 = v[2 * cc + 1];
                float v8 = v[2 * cc + 8], v9 = v[2 * cc + 9];
                __nv_bfloat162 ha = __floats2bfloat162_rn(v0, v1);
                __nv_bfloat162 hb = __floats2bfloat162_rn(v8, v9);
                float2 fa = __bfloat1622float2(ha);
                float2 fb = __bfloat1622float2(hb);
                __nv_bfloat162 la = __floats2bfloat162_rn(v0 - fa.x, v1 - fa.y);
                __nv_bfloat162 lb = __floats2bfloat162_rn(v8 - fb.x, v9 - fb.y);
                *(uint2*)(h16h + tid * 32 + cc * 8) = make_uint2(b2u(ha), b2u(hb));
                *(uint2*)(h16l + tid * 32 + cc * 8) = make_uint2(b2u(la), b2u(lb));
            }
        }
        __syncthreads();   // h16 ready; h_s32 free

        if (kc < 7) {
            const float* src = hrow + (kc + 1) * 16;
            #pragma unroll
            for (int i = 0; i < 4; i++)
                cp_async16(hdst + i * 16, src + i * 4);
            CP_COMMIT();
        }

        // A fragments (W bf16 hi/lo): 4 x LDS.64
        const int wkoff = kc * 16 + c * 4;
        uint2 wh0 = *(const uint2*)((char*)Wh16 + (row0 * WS16 + wkoff) * 2);
        uint2 wh1 = *(const uint2*)((char*)Wh16 + ((row0 + 8) * WS16 + wkoff) * 2);
        uint2 wl0 = *(const uint2*)((char*)Wl16 + (row0 * WS16 + wkoff) * 2);
        uint2 wl1 = *(const uint2*)((char*)Wl16 + ((row0 + 8) * WS16 + wkoff) * 2);

        #pragma unroll
        for (int nf = 0; nf < 16; nf++) {
            const int m = mq * 128 + nf * 8 + q;
            uint2 bhv = *(const uint2*)(h16h + m * 32 + c * 8);
            uint2 blv = *(const uint2*)(h16l + m * 32 + c * 8);
            mma_bf16(acc[nf], wh0.x, wh1.x, wh0.y, wh1.y, bhv.x, bhv.y); // hi*hi
            mma_bf16(acc[nf], wl0.x, wl1.x, wl0.y, wl1.y, bhv.x, bhv.y); // lo*hi
            mma_bf16(acc[nf], wh0.x, wh1.x, wh0.y, wh1.y, blv.x, blv.y); // hi*lo
        }
    }

    // Store acc -> hpT (fp16, permuted m):
    //   logical m = mq*128 + nf*8 + 2c + j  ->  phys = mq*128 + (nf>>1)*16 + c*4 + (nf&1)*2 + j
    {
        char* r0p = (char*)hpT + (row0 * HPTH_S + mq * 128 + c * 4) * 2;
        char* r1p = r0p + 8 * HPTH_S * 2;
        #pragma unroll
        for (int nf = 0; nf < 16; nf++) {
            const int off = ((nf >> 1) * 16 + (nf & 1) * 2) * 2;
            __half2 p0 = __floats2half2_rn(acc[nf][0], acc[nf][1]);
            __half2 p1 = __floats2half2_rn(acc[nf][2], acc[nf][3]);
            *(uint32_t*)(r0p + off) = h2u(p0);
            *(uint32_t*)(r1p + off) = h2u(p1);
        }
    }
    __syncthreads();

    // =================== Phase 1.5: e-scores (+ shift) ===================
    {
        const int w = tid & 15;
        const int a = (tid & ~15) | (((w >> 1) & 1) << 3) | ((w >> 2) << 1) | (w & 1);
        float es = 0.f, ed = 0.f;
        #pragma unroll
        for (int d = 0; d < 64; d++) {
            float hp = __half2float(hpT[d * HPTH_S + tid]);
            es += hp * a_s[d];
            ed += hp * a_s[64 + d];
        }
        float* ep = (float*)&Edp[a >> 1];
        const int j = a & 1;
        ep[j]     = ex2(ed * LOG2E);
        ep[2 + j] = ex2(ed * (NEG_SLOPE * LOG2E));

        // global edmax (log domain) for the fp16-safe shift
        float em = ed;
        #pragma unroll
        for (int o = 16; o; o >>= 1)
            em = fmaxf(em, __shfl_xor_sync(0xFFFFFFFFu, em, o));
        if (lane == 0) red_s[warp] = em;
        __syncthreads();
        em = red_s[0];
        #pragma unroll
        for (int i = 1; i < 16; i++) em = fmaxf(em, red_s[i]);

        const float e0 = es + em;
        const float rm = fmaxf(e0, NEG_SLOPE * e0) * LOG2E;   // rowmax * log2e
        Es_s[a]   = ex2(es * LOG2E - rm);
        Es02_s[a] = ex2(es * (NEG_SLOPE * LOG2E) - rm);
    }
    __syncthreads();

    // =================== Phase 2: attention (fp16 k16) ===================
    const int r0 = (warp >> 3) * 256 + (warp & 7) * 32 + q;
    const float EsA0 = Es_s[r0],        EsA1 = Es_s[r0 + 8];
    const float EtA0 = Es02_s[r0],      EtA1 = Es02_s[r0 + 8];
    const float EsB0 = Es_s[r0 + 16],   EsB1 = Es_s[r0 + 24];
    const float EtB0 = Es02_s[r0 + 16], EtB1 = Es02_s[r0 + 24];

    float dA[8][4], dB[8][4];
    #pragma unroll
    for (int t = 0; t < 8; t++)
        #pragma unroll
        for (int j = 0; j < 4; j++) { dA[t][j] = 0.f; dB[t][j] = 0.f; }

    float sA0 = 0.f, sA1 = 0.f, sB0 = 0.f, sB1 = 0.f;
    const char* bbase = (const char*)hpT + (q * HPTH_S + c * 4) * 2;

    #pragma unroll 2
    for (int K = 0; K < 32; K++) {
        const float4 e0 = Edp[K * 8 + c];       // m = K*16+2c, +1
        const float4 e1 = Edp[K * 8 + c + 4];   // m = K*16+8+2c, +1

        // 16 weights: w = max(Es'*Ed, Es02'*Ed02)  (shifted, <= 1)
        float wA0x = fmaxf(EsA0 * e0.x, EtA0 * e0.z);
        float wA0y = fmaxf(EsA0 * e0.y, EtA0 * e0.w);
        float wA0z = fmaxf(EsA0 * e1.x, EtA0 * e1.z);
        float wA0w = fmaxf(EsA0 * e1.y, EtA0 * e1.w);
        float wA1x = fmaxf(EsA1 * e0.x, EtA1 * e0.z);
        float wA1y = fmaxf(EsA1 * e0.y, EtA1 * e0.w);
        float wA1z = fmaxf(EsA1 * e1.x, EtA1 * e1.z);
        float wA1w = fmaxf(EsA1 * e1.y, EtA1 * e1.w);
        float wB0x = fmaxf(EsB0 * e0.x, EtB0 * e0.z);
        float wB0y = fmaxf(EsB0 * e0.y, EtB0 * e0.w);
        float wB0z = fmaxf(EsB0 * e1.x, EtB0 * e1.z);
        float wB0w = fmaxf(EsB0 * e1.y, EtB0 * e1.w);
        float wB1x = fmaxf(EsB1 * e0.x, EtB1 * e0.z);
        float wB1y = fmaxf(EsB1 * e0.y, EtB1 * e0.w);
        float wB1z = fmaxf(EsB1 * e1.x, EtB1 * e1.z);
        float wB1w = fmaxf(EsB1 * e1.y, EtB1 * e1.w);

        sA0 += (wA0x + wA0y) + (wA0z + wA0w);
        sA1 += (wA1x + wA1y) + (wA1z + wA1w);
        sB0 += (wB0x + wB0y) + (wB0z + wB0w);
        sB1 += (wB1x + wB1y) + (wB1z + wB1w);

        const uint32_t a0 = h2u(__floats2half2_rn(wA0x, wA0y));
        const uint32_t a1 = h2u(__floats2half2_rn(wA1x, wA1y));
        const uint32_t a2 = h2u(__floats2half2_rn(wA0z, wA0w));
        const uint32_t a3 = h2u(__floats2half2_rn(wA1z, wA1w));
        const uint32_t a4 = h2u(__floats2half2_rn(wB0x, wB0y));
        const uint32_t a5 = h2u(__floats2half2_rn(wB1x, wB1y));
        const uint32_t a6 = h2u(__floats2half2_rn(wB0z, wB0w));
        const uint32_t a7 = h2u(__floats2half2_rn(wB1z, wB1w));

        const char* bk = bbase + K * 32;
        #pragma unroll
        for (int dtf = 0; dtf < 8; dtf++) {
            const uint2 b2 = *(const uint2*)(bk + dtf * (8 * HPTH_S * 2));
            mma_f16(dA[dtf], a0, a1, a2, a3, b2.x, b2.y);
            mma_f16(dB[dtf], a4, a5, a6, a7, b2.x, b2.y);
        }
    }

    // Row sums: reduce over the 4 k-lanes
    sA0 += __shfl_xor_sync(0xFFFFFFFFu, sA0, 1); sA0 += __shfl_xor_sync(0xFFFFFFFFu, sA0, 2);
    sA1 += __shfl_xor_sync(0xFFFFFFFFu, sA1, 1); sA1 += __shfl_xor_sync(0xFFFFFFFFu, sA1, 2);
    sB0 += __shfl_xor_sync(0xFFFFFFFFu, sB0, 1); sB0 += __shfl_xor_sync(0xFFFFFFFFu, sB0, 2);
    sB1 += __shfl_xor_sync(0xFFFFFFFFu, sB1, 1); sB1 += __shfl_xor_sync(0xFFFFFFFFu, sB1, 2);
    const float ivA0 = 1.f / sA0, ivA1 = 1.f / sA1;
    const float ivB0 = 1.f / sB0, ivB1 = 1.f / sB1;

    // Epilogue: normalize + ELU + store
    const size_t orow = ((size_t)bh * NA + r0) * HD;
    float* o0 = out + orow;                 // row r0
    float* o1 = o0 + 8 * HD;                // r0+8
    float* o2 = o0 + 16 * HD;               // r0+16
    float* o3 = o0 + 24 * HD;               // r0+24
    #pragma unroll
    for (int dtf = 0; dtf < 8; dtf++) {
        const int dc = dtf * 8 + 2 * c;
        float2 v;
        v.x = elu1(dA[dtf][0] * ivA0); v.y = elu1(dA[dtf][1] * ivA0);
        *(float2*)&o0[dc] = v;
        v.x = elu1(dA[dtf][2] * ivA1); v.y = elu1(dA[dtf][3] * ivA1);
        *(float2*)&o1[dc] = v;
        v.x = elu1(dB[dtf][0] * ivB0); v.y = elu1(dB[dtf][1] * ivB0);
        *(float2*)&o2[dc] = v;
        v.x = elu1(dB[dtf][2] * ivB1); v.y = elu1(dB[dtf][3] * ivB1);
        *(float2*)&o3[dc] = v;
    }
}

// ---------------------------------------------------------------------------
extern "C" void kernel_launch(void* const* d_in, const int* in_sizes, int n_in,
                              void* d_out, int out_size)
{
    const float* h     = (const float*)d_in[0];
    const float* W     = (const float*)d_in[1];
    const float* att_a = (const float*)d_in[2];
    float* out = (float*)d_out;

    cudaFuncSetAttribute(gat_fused_kernel,
        cudaFuncAttributeMaxDynamicSharedMemorySize, SMEM_F_BYTES);

    gat_fused_kernel<<<BS * NH, 512, SMEM_F_BYTES>>>(h, W, att_a, out);
}

// round 13
// speedup vs baseline: 1.8303x; 1.0468x over previous
#include <cuda_runtime.h>
#include <cuda_fp16.h>
#include <cuda_bf16.h>
#include <math.h>
#include <stdint.h>

#define NEG_SLOPE 0.2f
#define LOG2E 1.4426950408889634f

// Problem constants
#define BS 32
#define NA 512          // n_agents
#define ID 128          // input_dim
#define NH 8            // n_heads
#define HD 64           // hidden_dim

// ---------------------------------------------------------------------------
// helpers
// ---------------------------------------------------------------------------
__device__ __forceinline__ float ex2(float x) {
    float r;
    asm("ex2.approx.f32 %0, %1;" : "=f"(r) : "f"(x));
    return r;
}
__device__ __forceinline__ uint32_t smem_u32(const void* p) {
    uint32_t a;
    asm("{ .reg .u64 t; cvta.to.shared.u64 t, %1; cvt.u32.u64 %0, t; }"
        : "=r"(a) : "l"(p));
    return a;
}
__device__ __forceinline__ void cp_async16(uint32_t dst, const void* src) {
    asm volatile("cp.async.cg.shared.global [%0], [%1], 16;"
                 :: "r"(dst), "l"(src) : "memory");
}
#define CP_COMMIT() asm volatile("cp.async.commit_group;" ::: "memory")
#define CP_WAIT0()  asm volatile("cp.async.wait_group 0;" ::: "memory")

__device__ __forceinline__ void mma_f16(float d[4], uint32_t a0, uint32_t a1,
                                        uint32_t a2, uint32_t a3,
                                        uint32_t b0, uint32_t b1) {
    asm volatile(
        "mma.sync.aligned.m16n8k16.row.col.f32.f16.f16.f32 "
        "{%0,%1,%2,%3}, {%4,%5,%6,%7}, {%8,%9}, {%0,%1,%2,%3};"
        : "+f"(d[0]), "+f"(d[1]), "+f"(d[2]), "+f"(d[3])
        : "r"(a0), "r"(a1), "r"(a2), "r"(a3), "r"(b0), "r"(b1));
}
__device__ __forceinline__ void mma_bf16(float d[4], uint32_t a0, uint32_t a1,
                                         uint32_t a2, uint32_t a3,
                                         uint32_t b0, uint32_t b1) {
    asm volatile(
        "mma.sync.aligned.m16n8k16.row.col.f32.bf16.bf16.f32 "
        "{%0,%1,%2,%3}, {%4,%5,%6,%7}, {%8,%9}, {%0,%1,%2,%3};"
        : "+f"(d[0]), "+f"(d[1]), "+f"(d[2]), "+f"(d[3])
        : "r"(a0), "r"(a1), "r"(a2), "r"(a3), "r"(b0), "r"(b1));
}
__device__ __forceinline__ float elu1(float x) {
    return x > 0.f ? x : expm1f(x);
}
__device__ __forceinline__ uint32_t h2u(__half2 v) {
    return *reinterpret_cast<uint32_t*>(&v);
}
__device__ __forceinline__ uint32_t b2u(__nv_bfloat162 v) {
    return *reinterpret_cast<uint32_t*>(&v);
}
__device__ __forceinline__ uint32_t hmul2u(uint32_t x, uint32_t y) {
    __half2 r = __hmul2(*reinterpret_cast<__half2*>(&x),
                        *reinterpret_cast<__half2*>(&y));
    return h2u(r);
}
__device__ __forceinline__ uint32_t hmax2u(uint32_t x, uint32_t y) {
    __half2 r = __hmax2(*reinterpret_cast<__half2*>(&x),
                        *reinterpret_cast<__half2*>(&y));
    return h2u(r);
}

// ---------------------------------------------------------------------------
// SMEM layout (byte offsets). k/m within each 16-group are PERMUTED to match
// m16n8k16 fragments: phys c*4+{0,1,2,3} = logical {2c, 2c+1, 2c+8, 2c+9}.
// ---------------------------------------------------------------------------
#define HPTH_S 528          // hpT fp16 row stride
#define HS32 20             // fp32 h staging stride
#define WS16 136            // W bf16 row stride

#define OFF_HPT   0                                   // __half [64][528]
#define OFF_WH    (OFF_HPT + 64 * HPTH_S * 2)         // bf16 [64][136]
#define OFF_WL    (OFF_WH + 64 * WS16 * 2)
#define OFF_H16H  (OFF_WL + 64 * WS16 * 2)            // bf16 [512][16]
#define OFF_H16L  (OFF_H16H + 512 * 16 * 2)
#define OFF_HS32  (OFF_H16L + 512 * 16 * 2)           // float [512][20]
#define OFF_EDPH  (OFF_HS32 + 512 * HS32 * 4)         // half granules, 4KB
#define OFF_ES    (OFF_EDPH + 4096)                   // float [512]
#define OFF_ES02  (OFF_ES + 512 * 4)
#define OFF_AS    (OFF_ES02 + 512 * 4)                // float [128]
#define OFF_RED   (OFF_AS + 128 * 4)                  // float [16]
#define SMEM_F_BYTES (OFF_RED + 64 + 64)

__global__ void __launch_bounds__(512, 1) gat_fused_kernel(
    const float* __restrict__ h, const float* __restrict__ W,
    const float* __restrict__ att_a, float* __restrict__ out)
{
    extern __shared__ char smraw[];
    __half*         hpT  = (__half*)(smraw + OFF_HPT);
    __nv_bfloat16*  Wh16 = (__nv_bfloat16*)(smraw + OFF_WH);
    __nv_bfloat16*  Wl16 = (__nv_bfloat16*)(smraw + OFF_WL);
    char*           h16h = smraw + OFF_H16H;
    char*           h16l = smraw + OFF_H16L;
    float*          h_s32 = (float*)(smraw + OFF_HS32);
    char*           edpB = smraw + OFF_EDPH;
    float*          Es_s = (float*)(smraw + OFF_ES);
    float*          Es02_s = (float*)(smraw + OFF_ES02);
    float*          a_s  = (float*)(smraw + OFF_AS);
    float*          red_s = (float*)(smraw + OFF_RED);

    const int bh = blockIdx.x;
    const int head = bh & 7;
    const int b = bh >> 3;
    const int col0 = head * HD;
    const int tid = threadIdx.x;
    const int warp = tid >> 5;
    const int lane = tid & 31;
    const int q = lane >> 2;       // group id
    const int c = lane & 3;        // thread-in-group

    if (tid < 128) a_s[tid] = att_a[head * 128 + tid];

    // ---- Stage & split W into bf16 hi/lo (permuted k), once ----
    #pragma unroll 4
    for (int i = 0; i < 16; i++) {
        int idx = tid + i * 512;
        int d = idx & 63, k = idx >> 6;
        float v = W[(size_t)k * 512 + col0 + d];
        __nv_bfloat16 hi = __float2bfloat16_rn(v);
        __nv_bfloat16 lo = __float2bfloat16_rn(v - __bfloat162float(hi));
        int L = k & 15;
        int pk = (k & ~15) + ((L >> 1) & 3) * 4 + (L >> 3) * 2 + (L & 1);
        Wh16[d * WS16 + pk] = hi;
        Wl16[d * WS16 + pk] = lo;
    }

    // ---- prologue: cp.async chunk 0 of h (fp32) ----
    const float* hrow = h + ((size_t)(b * NA) + tid) * ID;
    const uint32_t hdst = smem_u32(h_s32) + tid * (HS32 * 4);
    #pragma unroll
    for (int i = 0; i < 4; i++)
        cp_async16(hdst + i * 16, hrow + i * 4);
    CP_COMMIT();

    // ======================= Phase 1: GEMM -> hpT =======================
    const int dt = warp & 3;
    const int mq = warp >> 2;
    const int row0 = dt * 16 + q;

    float acc[16][4];
    #pragma unroll
    for (int f = 0; f < 16; f++)
        #pragma unroll
        for (int j = 0; j < 4; j++) acc[f][j] = 0.f;

    for (int kc = 0; kc < 8; kc++) {
        CP_WAIT0();
        __syncthreads();

        // split own row's 16 values -> bf16 hi/lo (permuted)
        {
            float v[16];
            #pragma unroll
            for (int i = 0; i < 4; i++)
                *(float4*)&v[i * 4] = *(const float4*)&h_s32[tid * HS32 + i * 4];
            #pragma unroll
            for (int cc = 0; cc < 4; cc++) {
                float v0 = v[2 * cc], v1 = v[2 * cc + 1];
                float v8 = v[2 * cc + 8], v9 = v[2 * cc + 9];
                __nv_bfloat162 ha = __floats2bfloat162_rn(v0, v1);
                __nv_bfloat162 hb = __floats2bfloat162_rn(v8, v9);
                float2 fa = __bfloat1622float2(ha);
                float2 fb = __bfloat1622float2(hb);
                __nv_bfloat162 la = __floats2bfloat162_rn(v0 - fa.x, v1 - fa.y);
                __nv_bfloat162 lb = __floats2bfloat162_rn(v8 - fb.x, v9 - fb.y);
                *(uint2*)(h16h + tid * 32 + cc * 8) = make_uint2(b2u(ha), b2u(hb));
                *(uint2*)(h16l + tid * 32 + cc * 8) = make_uint2(b2u(la), b2u(lb));
            }
        }
        __syncthreads();

        if (kc < 7) {
            const float* src = hrow + (kc + 1) * 16;
            #pragma unroll
            for (int i = 0; i < 4; i++)
                cp_async16(hdst + i * 16, src + i * 4);
            CP_COMMIT();
        }

        const int wkoff = kc * 16 + c * 4;
        uint2 wh0 = *(const uint2*)((char*)Wh16 + (row0 * WS16 + wkoff) * 2);
        uint2 wh1 = *(const uint2*)((char*)Wh16 + ((row0 + 8) * WS16 + wkoff) * 2);
        uint2 wl0 = *(const uint2*)((char*)Wl16 + (row0 * WS16 + wkoff) * 2);
        uint2 wl1 = *(const uint2*)((char*)Wl16 + ((row0 + 8) * WS16 + wkoff) * 2);

        #pragma unroll
        for (int nf = 0; nf < 16; nf++) {
            const int m = mq * 128 + nf * 8 + q;
            uint2 bhv = *(const uint2*)(h16h + m * 32 + c * 8);
            uint2 blv = *(const uint2*)(h16l + m * 32 + c * 8);
            mma_bf16(acc[nf], wh0.x, wh1.x, wh0.y, wh1.y, bhv.x, bhv.y);
            mma_bf16(acc[nf], wl0.x, wl1.x, wl0.y, wl1.y, bhv.x, bhv.y);
            mma_bf16(acc[nf], wh0.x, wh1.x, wh0.y, wh1.y, blv.x, blv.y);
        }
    }

    // Store acc -> hpT (fp16, permuted m)
    {
        char* r0p = (char*)hpT + (row0 * HPTH_S + mq * 128 + c * 4) * 2;
        char* r1p = r0p + 8 * HPTH_S * 2;
        #pragma unroll
        for (int nf = 0; nf < 16; nf++) {
            const int off = ((nf >> 1) * 16 + (nf & 1) * 2) * 2;
            __half2 p0 = __floats2half2_rn(acc[nf][0], acc[nf][1]);
            __half2 p1 = __floats2half2_rn(acc[nf][2], acc[nf][3]);
            *(uint32_t*)(r0p + off) = h2u(p0);
            *(uint32_t*)(r1p + off) = h2u(p1);
        }
    }
    __syncthreads();

    // =================== Phase 1.5: e-scores (+ shift, fp16 factors) =====
    {
        const int w = tid & 15;
        const int a = (tid & ~15) | (((w >> 1) & 1) << 3) | ((w >> 2) << 1) | (w & 1);
        float es = 0.f, ed = 0.f;
        #pragma unroll
        for (int d = 0; d < 64; d++) {
            float hp = __half2float(hpT[d * HPTH_S + tid]);
            es += hp * a_s[d];
            ed += hp * a_s[64 + d];
        }

        // global edmax
        float em = ed;
        #pragma unroll
        for (int o = 16; o; o >>= 1)
            em = fmaxf(em, __shfl_xor_sync(0xFFFFFFFFu, em, o));
        if (lane == 0) red_s[warp] = em;
        __syncthreads();
        em = red_s[0];
        #pragma unroll
        for (int i = 1; i < 16; i++) em = fmaxf(em, red_s[i]);

        // Ed' = 2^((ed-em)L2E) <= 1 ; Ed02' = 2^(0.2(ed-em)L2E) <= 1
        const float edl = (ed - em) * LOG2E;
        const __half Edh   = __float2half_rn(ex2(edl));
        const __half Ed02h = __float2half_rn(ex2(NEG_SLOPE * edl));
        // physical placement: granule g = K*8 + cc*2 + s (8B each)
        {
            const int K = a >> 4, s = (a >> 3) & 1, cc = (a >> 1) & 3, j = a & 1;
            char* g = edpB + (K * 8 + cc * 2 + s) * 8;
            *(__half*)(g + j * 2)     = Edh;
            *(__half*)(g + 4 + j * 2) = Ed02h;
        }

        // Es' = 2^((es+em)L2E - rm) <= 1 ; Es02' = 2^(0.2(es+em)L2E - rm) <= 1
        const float e0l = (es + em) * LOG2E;
        const float rm = fmaxf(e0l, NEG_SLOPE * e0l);
        Es_s[a]   = ex2(es * LOG2E + em * LOG2E - rm);
        Es02_s[a] = ex2(NEG_SLOPE * e0l - rm);
    }
    __syncthreads();

    // =================== Phase 2: attention (fp16 k16, packed A-gen) =====
    const int r0 = (warp >> 3) * 256 + (warp & 7) * 32 + q;
    const uint32_t EsA0h = h2u(__float2half2_rn(Es_s[r0]));
    const uint32_t EsA1h = h2u(__float2half2_rn(Es_s[r0 + 8]));
    const uint32_t EsB0h = h2u(__float2half2_rn(Es_s[r0 + 16]));
    const uint32_t EsB1h = h2u(__float2half2_rn(Es_s[r0 + 24]));
    const uint32_t EtA0h = h2u(__float2half2_rn(Es02_s[r0]));
    const uint32_t EtA1h = h2u(__float2half2_rn(Es02_s[r0 + 8]));
    const uint32_t EtB0h = h2u(__float2half2_rn(Es02_s[r0 + 16]));
    const uint32_t EtB1h = h2u(__float2half2_rn(Es02_s[r0 + 24]));
    const uint32_t ONE2 = 0x3C003C00u;

    float dA[8][4], dB[8][4], dSA[4], dSB[4];
    #pragma unroll
    for (int t = 0; t < 8; t++)
        #pragma unroll
        for (int j = 0; j < 4; j++) { dA[t][j] = 0.f; dB[t][j] = 0.f; }
    #pragma unroll
    for (int j = 0; j < 4; j++) { dSA[j] = 0.f; dSB[j] = 0.f; }

    const char* bbase = (const char*)hpT + (q * HPTH_S + c * 4) * 2;
    const char* eb = edpB + c * 16;

    #pragma unroll 2
    for (int K = 0; K < 32; K++) {
        const uint4 e4 = *(const uint4*)(eb + K * 64);
        // slab0: e4.x=EdH, e4.y=Ed02H ; slab1: e4.z, e4.w
        const uint32_t a0 = hmax2u(hmul2u(EsA0h, e4.x), hmul2u(EtA0h, e4.y));
        const uint32_t a1 = hmax2u(hmul2u(EsA1h, e4.x), hmul2u(EtA1h, e4.y));
        const uint32_t a2 = hmax2u(hmul2u(EsA0h, e4.z), hmul2u(EtA0h, e4.w));
        const uint32_t a3 = hmax2u(hmul2u(EsA1h, e4.z), hmul2u(EtA1h, e4.w));
        const uint32_t a4 = hmax2u(hmul2u(EsB0h, e4.x), hmul2u(EtB0h, e4.y));
        const uint32_t a5 = hmax2u(hmul2u(EsB1h, e4.x), hmul2u(EtB1h, e4.y));
        const uint32_t a6 = hmax2u(hmul2u(EsB0h, e4.z), hmul2u(EtB0h, e4.w));
        const uint32_t a7 = hmax2u(hmul2u(EsB1h, e4.z), hmul2u(EtB1h, e4.w));

        // row sums via ones-column MMA (exact fp32, consistent with weights)
        mma_f16(dSA, a0, a1, a2, a3, ONE2, ONE2);
        mma_f16(dSB, a4, a5, a6, a7, ONE2, ONE2);

        const char* bk = bbase + K * 32;
        #pragma unroll
        for (int dtf = 0; dtf < 8; dtf++) {
            const uint2 b2 = *(const uint2*)(bk + dtf * (8 * HPTH_S * 2));
            mma_f16(dA[dtf], a0, a1, a2, a3, b2.x, b2.y);
            mma_f16(dB[dtf], a4, a5, a6, a7, b2.x, b2.y);
        }
    }

    const float ivA0 = 1.f / dSA[0], ivA1 = 1.f / dSA[2];
    const float ivB0 = 1.f / dSB[0], ivB1 = 1.f / dSB[2];

    // Epilogue: normalize + ELU + store
    const size_t orow = ((size_t)bh * NA + r0) * HD;
    float* o0 = out + orow;                 // row r0
    float* o1 = o0 + 8 * HD;                // r0+8
    float* o2 = o0 + 16 * HD;               // r0+16
    float* o3 = o0 + 24 * HD;               // r0+24
    #pragma unroll
    for (int dtf = 0; dtf < 8; dtf++) {
        const int dc = dtf * 8 + 2 * c;
        float2 v;
        v.x = elu1(dA[dtf][0] * ivA0); v.y = elu1(dA[dtf][1] * ivA0);
        *(float2*)&o0[dc] = v;
        v.x = elu1(dA[dtf][2] * ivA1); v.y = elu1(dA[dtf][3] * ivA1);
        *(float2*)&o1[dc] = v;
        v.x = elu1(dB[dtf][0] * ivB0); v.y = elu1(dB[dtf][1] * ivB0);
        *(float2*)&o2[dc] = v;
        v.x = elu1(dB[dtf][2] * ivB1); v.y = elu1(dB[dtf][3] * ivB1);
        *(float2*)&o3[dc] = v;
    }
}

// ---------------------------------------------------------------------------
extern "C" void kernel_launch(void* const* d_in, const int* in_sizes, int n_in,
                              void* d_out, int out_size)
{
    const float* h     = (const float*)d_in[0];
    const float* W     = (const float*)d_in[1];
    const float* att_a = (const float*)d_in[2];
    float* out = (float*)d_out;

    cudaFuncSetAttribute(gat_fused_kernel,
        cudaFuncAttributeMaxDynamicSharedMemorySize, SMEM_F_BYTES);

    gat_fused_kernel<<<BS * NH, 512, SMEM_F_BYTES>>>(h, W, att_a, out);
}

// round 14
// speedup vs baseline: 2.2497x; 1.2291x over previous
#include <cuda_runtime.h>
#include <cuda_fp16.h>
#include <math.h>
#include <stdint.h>

#define NEG_SLOPE 0.2f
#define LOG2E 1.4426950408889634f

// Problem constants
#define BS 32
#define NA 512          // n_agents
#define ID 128          // input_dim
#define NH 8            // n_heads
#define HD 64           // hidden_dim

// ---------------------------------------------------------------------------
// helpers
// ---------------------------------------------------------------------------
__device__ __forceinline__ float ex2(float x) {
    float r;
    asm("ex2.approx.f32 %0, %1;" : "=f"(r) : "f"(x));
    return r;
}
__device__ __forceinline__ uint32_t smem_u32(const void* p) {
    uint32_t a;
    asm("{ .reg .u64 t; cvta.to.shared.u64 t, %1; cvt.u32.u64 %0, t; }"
        : "=r"(a) : "l"(p));
    return a;
}
__device__ __forceinline__ void cp_async16(uint32_t dst, const void* src) {
    asm volatile("cp.async.cg.shared.global [%0], [%1], 16;"
                 :: "r"(dst), "l"(src) : "memory");
}
#define CP_COMMIT() asm volatile("cp.async.commit_group;" ::: "memory")
#define CP_WAIT0()  asm volatile("cp.async.wait_group 0;" ::: "memory")
#define CP_WAIT1()  asm volatile("cp.async.wait_group 1;" ::: "memory")

__device__ __forceinline__ void mma_f16(float d[4], uint32_t a0, uint32_t a1,
                                        uint32_t a2, uint32_t a3,
                                        uint32_t b0, uint32_t b1) {
    asm volatile(
        "mma.sync.aligned.m16n8k16.row.col.f32.f16.f16.f32 "
        "{%0,%1,%2,%3}, {%4,%5,%6,%7}, {%8,%9}, {%0,%1,%2,%3};"
        : "+f"(d[0]), "+f"(d[1]), "+f"(d[2]), "+f"(d[3])
        : "r"(a0), "r"(a1), "r"(a2), "r"(a3), "r"(b0), "r"(b1));
}
__device__ __forceinline__ float elu1(float x) {
    return x > 0.f ? x : expm1f(x);
}
__device__ __forceinline__ uint32_t h2u(__half2 v) {
    return *reinterpret_cast<uint32_t*>(&v);
}
__device__ __forceinline__ uint32_t hmul2u(uint32_t x, uint32_t y) {
    __half2 r = __hmul2(*reinterpret_cast<__half2*>(&x),
                        *reinterpret_cast<__half2*>(&y));
    return h2u(r);
}
__device__ __forceinline__ uint32_t hmax2u(uint32_t x, uint32_t y) {
    __half2 r = __hmax2(*reinterpret_cast<__half2*>(&x),
                        *reinterpret_cast<__half2*>(&y));
    return h2u(r);
}

// ---------------------------------------------------------------------------
// SMEM layout (byte offsets). k/m within each 16-group are PERMUTED to match
// m16n8k16 fragments: phys c*4+{0,1,2,3} = logical {2c, 2c+1, 2c+8, 2c+9}.
// ---------------------------------------------------------------------------
#define HPTH_S 528          // hpT fp16 row stride
#define HS32 20             // fp32 h staging stride (80B rows)
#define WS16 136            // W fp16 row stride

#define OFF_HPT   0                                   // half [64][528]   67584
#define OFF_WH    (OFF_HPT + 64 * HPTH_S * 2)         // half [64][136]   17408
#define OFF_H16   (OFF_WH + 64 * WS16 * 2)            // half [2][512][16] 32768
#define OFF_HS32  (OFF_H16 + 2 * 512 * 16 * 2)        // float [2][512][20] 81920
#define OFF_EDPH  (OFF_HS32 + 2 * 512 * HS32 * 4)     // 2048 + 64 pad
#define OFF_ES    (OFF_EDPH + 2048 + 64)              // float [512]
#define OFF_ES02  (OFF_ES + 2048)
#define OFF_AS    (OFF_ES02 + 2048)                   // float [128]
#define OFF_RED   (OFF_AS + 512)                      // float [16]
#define SMEM_F_BYTES (OFF_RED + 64 + 64)              // ~206.5 KB

__global__ void __launch_bounds__(512, 1) gat_fused_kernel(
    const float* __restrict__ h, const float* __restrict__ W,
    const float* __restrict__ att_a, float* __restrict__ out)
{
    extern __shared__ char smraw[];
    __half* hpT   = (__half*)(smraw + OFF_HPT);
    __half* Wh16  = (__half*)(smraw + OFF_WH);
    char*   h16   = smraw + OFF_H16;      // 2 bufs x [512][16] half
    float*  h_s32 = (float*)(smraw + OFF_HS32);
    char*   edpB  = smraw + OFF_EDPH;
    float*  Es_s  = (float*)(smraw + OFF_ES);
    float*  Es02_s = (float*)(smraw + OFF_ES02);
    float*  a_s   = (float*)(smraw + OFF_AS);
    float*  red_s = (float*)(smraw + OFF_RED);

    const int bh = blockIdx.x;
    const int head = bh & 7;
    const int b = bh >> 3;
    const int col0 = head * HD;
    const int tid = threadIdx.x;
    const int warp = tid >> 5;
    const int lane = tid & 31;
    const int q = lane >> 2;       // group id
    const int c = lane & 3;        // thread-in-group

    if (tid < 128) a_s[tid] = att_a[head * 128 + tid];

    // ---- Stage W as fp16 (permuted k), once ----
    #pragma unroll 4
    for (int i = 0; i < 16; i++) {
        int idx = tid + i * 512;
        int d = idx & 63, k = idx >> 6;
        float v = W[(size_t)k * 512 + col0 + d];
        int L = k & 15;
        int pk = (k & ~15) + ((L >> 1) & 3) * 4 + (L >> 3) * 2 + (L & 1);
        Wh16[d * WS16 + pk] = __float2half_rn(v);
    }

    // ---- Phase-1 staging pipeline (cp.async 2 ahead, h16 double buffer) ----
    const float* hrow = h + ((size_t)(b * NA) + tid) * ID;
    const uint32_t hdst = smem_u32(h_s32) + tid * (HS32 * 4);
    const uint32_t hbufstep = 512 * HS32 * 4;

    #pragma unroll
    for (int i = 0; i < 4; i++)                    // chunk 0 -> buf 0
        cp_async16(hdst + i * 16, hrow + i * 4);
    CP_COMMIT();
    #pragma unroll
    for (int i = 0; i < 4; i++)                    // chunk 1 -> buf 1
        cp_async16(hdst + hbufstep + i * 16, hrow + 16 + i * 4);
    CP_COMMIT();

    // convert chunk 0 -> h16 buf 0
    CP_WAIT1();
    {
        float v[16];
        #pragma unroll
        for (int i = 0; i < 4; i++)
            *(float4*)&v[i * 4] = *(const float4*)&h_s32[tid * HS32 + i * 4];
        #pragma unroll
        for (int cc = 0; cc < 4; cc++) {
            __half2 ha = __floats2half2_rn(v[2 * cc], v[2 * cc + 1]);
            __half2 hb = __floats2half2_rn(v[2 * cc + 8], v[2 * cc + 9]);
            *(uint2*)(h16 + tid * 32 + cc * 8) = make_uint2(h2u(ha), h2u(hb));
        }
    }
    __syncthreads();

    // ======================= Phase 1: GEMM -> hpT (plain fp16) ==========
    const int dt = warp & 3;
    const int mq = warp >> 2;
    const int row0 = dt * 16 + q;

    float acc[16][4];
    #pragma unroll
    for (int f = 0; f < 16; f++)
        #pragma unroll
        for (int j = 0; j < 4; j++) acc[f][j] = 0.f;

    for (int kc = 0; kc < 8; kc++) {
        // keep cp 2 chunks ahead
        if (kc < 6) {
            const float* src = hrow + (kc + 2) * 16;
            const uint32_t dst = hdst + (kc & 1) * hbufstep;
            #pragma unroll
            for (int i = 0; i < 4; i++)
                cp_async16(dst + i * 16, src + i * 4);
            CP_COMMIT();
        }
        // convert chunk kc+1 into h16 buf (kc+1)&1 (off the MMA path)
        if (kc < 7) {
            if (kc < 6) { CP_WAIT1(); } else { CP_WAIT0(); }
            const float* sb = h_s32 + ((kc + 1) & 1) * (512 * HS32) + tid * HS32;
            char* db = h16 + ((kc + 1) & 1) * 16384 + tid * 32;
            float v[16];
            #pragma unroll
            for (int i = 0; i < 4; i++)
                *(float4*)&v[i * 4] = *(const float4*)&sb[i * 4];
            #pragma unroll
            for (int cc = 0; cc < 4; cc++) {
                __half2 ha = __floats2half2_rn(v[2 * cc], v[2 * cc + 1]);
                __half2 hb = __floats2half2_rn(v[2 * cc + 8], v[2 * cc + 9]);
                *(uint2*)(db + cc * 8) = make_uint2(h2u(ha), h2u(hb));
            }
        }

        // MMAs on chunk kc from h16 buf kc&1
        const int wkoff = kc * 16 + c * 4;
        uint2 wh0 = *(const uint2*)((char*)Wh16 + (row0 * WS16 + wkoff) * 2);
        uint2 wh1 = *(const uint2*)((char*)Wh16 + ((row0 + 8) * WS16 + wkoff) * 2);
        const char* hb16 = h16 + (kc & 1) * 16384;
        #pragma unroll
        for (int nf = 0; nf < 16; nf++) {
            const int m = mq * 128 + nf * 8 + q;
            uint2 bhv = *(const uint2*)(hb16 + m * 32 + c * 8);
            mma_f16(acc[nf], wh0.x, wh1.x, wh0.y, wh1.y, bhv.x, bhv.y);
        }
        __syncthreads();   // h16[(kc+1)&1] published; buf kc&1 free for reuse
    }

    // Store acc -> hpT (fp16, permuted m)
    {
        char* r0p = (char*)hpT + (row0 * HPTH_S + mq * 128 + c * 4) * 2;
        char* r1p = r0p + 8 * HPTH_S * 2;
        #pragma unroll
        for (int nf = 0; nf < 16; nf++) {
            const int off = ((nf >> 1) * 16 + (nf & 1) * 2) * 2;
            __half2 p0 = __floats2half2_rn(acc[nf][0], acc[nf][1]);
            __half2 p1 = __floats2half2_rn(acc[nf][2], acc[nf][3]);
            *(uint32_t*)(r0p + off) = h2u(p0);
            *(uint32_t*)(r1p + off) = h2u(p1);
        }
    }
    __syncthreads();

    // =================== Phase 1.5: e-scores (+ shift, fp16 factors) =====
    {
        const int w = tid & 15;
        const int a = (tid & ~15) | (((w >> 1) & 1) << 3) | ((w >> 2) << 1) | (w & 1);
        float es = 0.f, ed = 0.f;
        #pragma unroll
        for (int d = 0; d < 64; d++) {
            float hp = __half2float(hpT[d * HPTH_S + tid]);
            es += hp * a_s[d];
            ed += hp * a_s[64 + d];
        }

        // global edmax
        float em = ed;
        #pragma unroll
        for (int o = 16; o; o >>= 1)
            em = fmaxf(em, __shfl_xor_sync(0xFFFFFFFFu, em, o));
        if (lane == 0) red_s[warp] = em;
        __syncthreads();
        em = red_s[0];
        #pragma unroll
        for (int i = 1; i < 16; i++) em = fmaxf(em, red_s[i]);

        // Ed' = 2^((ed-em)L2E) <= 1 ; Ed02' = 2^(0.2(ed-em)L2E) <= 1
        const float edl = (ed - em) * LOG2E;
        const __half Edh   = __float2half_rn(ex2(edl));
        const __half Ed02h = __float2half_rn(ex2(NEG_SLOPE * edl));
        {
            const int K = a >> 4, s = (a >> 3) & 1, cc = (a >> 1) & 3, j = a & 1;
            char* g = edpB + (K * 8 + cc * 2 + s) * 8;
            *(__half*)(g + j * 2)     = Edh;
            *(__half*)(g + 4 + j * 2) = Ed02h;
        }

        // Es' = 2^((es+em)L2E - rm) ; Es02' = 2^(0.2(es+em)L2E - rm)
        const float e0l = (es + em) * LOG2E;
        const float rm = fmaxf(e0l, NEG_SLOPE * e0l);
        Es_s[a]   = ex2(es * LOG2E + em * LOG2E - rm);
        Es02_s[a] = ex2(NEG_SLOPE * e0l - rm);
    }
    __syncthreads();

    // =================== Phase 2: attention (fp16 k16, packed A-gen) =====
    const int r0 = (warp >> 3) * 256 + (warp & 7) * 32 + q;
    const uint32_t EsA0h = h2u(__float2half2_rn(Es_s[r0]));
    const uint32_t EsA1h = h2u(__float2half2_rn(Es_s[r0 + 8]));
    const uint32_t EsB0h = h2u(__float2half2_rn(Es_s[r0 + 16]));
    const uint32_t EsB1h = h2u(__float2half2_rn(Es_s[r0 + 24]));
    const uint32_t EtA0h = h2u(__float2half2_rn(Es02_s[r0]));
    const uint32_t EtA1h = h2u(__float2half2_rn(Es02_s[r0 + 8]));
    const uint32_t EtB0h = h2u(__float2half2_rn(Es02_s[r0 + 16]));
    const uint32_t EtB1h = h2u(__float2half2_rn(Es02_s[r0 + 24]));
    const uint32_t ONE2 = 0x3C003C00u;

    float dA[8][4], dB[8][4], dSA[4], dSB[4];
    #pragma unroll
    for (int t = 0; t < 8; t++)
        #pragma unroll
        for (int j = 0; j < 4; j++) { dA[t][j] = 0.f; dB[t][j] = 0.f; }
    #pragma unroll
    for (int j = 0; j < 4; j++) { dSA[j] = 0.f; dSB[j] = 0.f; }

    const char* bbase = (const char*)hpT + (q * HPTH_S + c * 4) * 2;
    const char* eb = edpB + c * 16;

    // e4 software pipeline: prefetch head of the dependency chain
    uint4 e4 = *(const uint4*)(eb);
    #pragma unroll 2
    for (int K = 0; K < 32; K++) {
        const uint4 e4n = *(const uint4*)(eb + (K + 1) * 64);  // K=31 overreads pad

        const uint32_t a0 = hmax2u(hmul2u(EsA0h, e4.x), hmul2u(EtA0h, e4.y));
        const uint32_t a1 = hmax2u(hmul2u(EsA1h, e4.x), hmul2u(EtA1h, e4.y));
        const uint32_t a2 = hmax2u(hmul2u(EsA0h, e4.z), hmul2u(EtA0h, e4.w));
        const uint32_t a3 = hmax2u(hmul2u(EsA1h, e4.z), hmul2u(EtA1h, e4.w));
        const uint32_t a4 = hmax2u(hmul2u(EsB0h, e4.x), hmul2u(EtB0h, e4.y));
        const uint32_t a5 = hmax2u(hmul2u(EsB1h, e4.x), hmul2u(EtB1h, e4.y));
        const uint32_t a6 = hmax2u(hmul2u(EsB0h, e4.z), hmul2u(EtB0h, e4.w));
        const uint32_t a7 = hmax2u(hmul2u(EsB1h, e4.z), hmul2u(EtB1h, e4.w));

        // row sums via ones-column MMA (fp32, consistent with used weights)
        mma_f16(dSA, a0, a1, a2, a3, ONE2, ONE2);
        mma_f16(dSB, a4, a5, a6, a7, ONE2, ONE2);

        const char* bk = bbase + K * 32;
        #pragma unroll
        for (int dtf = 0; dtf < 8; dtf++) {
            const uint2 b2 = *(const uint2*)(bk + dtf * (8 * HPTH_S * 2));
            mma_f16(dA[dtf], a0, a1, a2, a3, b2.x, b2.y);
            mma_f16(dB[dtf], a4, a5, a6, a7, b2.x, b2.y);
        }
        e4 = e4n;
    }

    const float ivA0 = 1.f / dSA[0], ivA1 = 1.f / dSA[2];
    const float ivB0 = 1.f / dSB[0], ivB1 = 1.f / dSB[2];

    // Epilogue: normalize + ELU + store
    const size_t orow = ((size_t)bh * NA + r0) * HD;
    float* o0 = out + orow;                 // row r0
    float* o1 = o0 + 8 * HD;                // r0+8
    float* o2 = o0 + 16 * HD;               // r0+16
    float* o3 = o0 + 24 * HD;               // r0+24
    #pragma unroll
    for (int dtf = 0; dtf < 8; dtf++) {
        const int dc = dtf * 8 + 2 * c;
        float2 v;
        v.x = elu1(dA[dtf][0] * ivA0); v.y = elu1(dA[dtf][1] * ivA0);
        *(float2*)&o0[dc] = v;
        v.x = elu1(dA[dtf][2] * ivA1); v.y = elu1(dA[dtf][3] * ivA1);
        *(float2*)&o1[dc] = v;
        v.x = elu1(dB[dtf][0] * ivB0); v.y = elu1(dB[dtf][1] * ivB0);
        *(float2*)&o2[dc] = v;
        v.x = elu1(dB[dtf][2] * ivB1); v.y = elu1(dB[dtf][3] * ivB1);
        *(float2*)&o3[dc] = v;
    }
}

// ---------------------------------------------------------------------------
extern "C" void kernel_launch(void* const* d_in, const int* in_sizes, int n_in,
                              void* d_out, int out_size)
{
    const float* h     = (const float*)d_in[0];
    const float* W     = (const float*)d_in[1];
    const float* att_a = (const float*)d_in[2];
    float* out = (float*)d_out;

    cudaFuncSetAttribute(gat_fused_kernel,
        cudaFuncAttributeMaxDynamicSharedMemorySize, SMEM_F_BYTES);

    gat_fused_kernel<<<BS * NH, 512, SMEM_F_BYTES>>>(h, W, att_a, out);
}